// round 13
// baseline (speedup 1.0000x reference)
#include <cuda_runtime.h>
#include <cuda_bf16.h>
#include <math.h>
#include <stdint.h>

#define T_   2048
#define D_   1024
#define NH   16
#define NKV  4
#define F_   2048
#define NE   8
#define NL   2
#define NV   32000
#define CH   512
#define NCK  4
#define QKV_ 1536

#define OUT_TASK   (T_*(size_t)NV)
#define OUT_EVAL   (OUT_TASK + 16)
#define OUT_AUX    (OUT_EVAL + 8)

typedef __nv_bfloat16 bf16;
typedef __nv_bfloat162 bf162;

// ---------------- scratch (device globals; no allocation) ----------------
__device__ float g_h   [(size_t)T_*D_];
__device__ float g_xn  [(size_t)T_*D_];
__device__ float g_qkv [(size_t)T_*QKV_];
__device__ float g_sc  [(size_t)NCK*NH*CH*CH];
__device__ float g_probs[(size_t)T_*NE];
__device__ int   g_ti  [T_*2];
__device__ float g_tw  [T_*2];
__device__ int   g_cnt [NE];
__device__ int   g_rows[NE*T_];
__device__ int   g_slot[T_*2];
__device__ float g_yb  [(size_t)NE*T_*D_];
__device__ float g_aux [1];
__device__ float g_xm  [D_];
__device__ float g_mp  [16*D_];
__device__ bf16  g_ah  [(size_t)T_*D_];
__device__ bf16  g_al  [(size_t)T_*D_];
__device__ bf16  g_qkvh[(size_t)T_*QKV_];
__device__ bf16  g_qkvl[(size_t)T_*QKV_];
__device__ bf16  g_hbh [(size_t)NE*T_*F_];   // also reused as P hi
__device__ bf16  g_hbl [(size_t)NE*T_*F_];   // also reused as P lo
// pre-converted weights (hi/lo bf16)
__device__ bf16  c_qkvh[(size_t)NL*D_*QKV_], c_qkvl[(size_t)NL*D_*QKV_];
__device__ bf16  c_woh [(size_t)NL*D_*D_],   c_wol [(size_t)NL*D_*D_];
__device__ bf16  c_w1h [(size_t)NL*NE*D_*F_], c_w1l[(size_t)NL*NE*D_*F_];
__device__ bf16  c_w3h [(size_t)NL*NE*D_*F_], c_w3l[(size_t)NL*NE*D_*F_];
__device__ bf16  c_w2h [(size_t)NL*NE*F_*D_], c_w2l[(size_t)NL*NE*F_*D_];
__device__ bf16  c_lmh [(size_t)D_*NV],      c_lml[(size_t)D_*NV];

// ---------------- asm helpers ----------------
__device__ __forceinline__ uint32_t smem_u32(const void* p) {
    uint32_t a;
    asm("{ .reg .u64 t; cvta.to.shared.u64 t, %1; cvt.u32.u64 %0, t; }" : "=r"(a) : "l"(p));
    return a;
}
__device__ __forceinline__ void cpa(uint32_t d, const void* s) {
    asm volatile("cp.async.cg.shared.global [%0], [%1], 16;" :: "r"(d), "l"(s));
}
__device__ __forceinline__ void cp_commit() { asm volatile("cp.async.commit_group;" ::: "memory"); }
__device__ __forceinline__ void cp_wait1()  { asm volatile("cp.async.wait_group 1;" ::: "memory"); }
__device__ __forceinline__ void cp_wait0()  { asm volatile("cp.async.wait_group 0;" ::: "memory"); }
__device__ __forceinline__ void ldsm4(uint32_t (&r)[4], uint32_t a) {
    asm volatile("ldmatrix.sync.aligned.m8n8.x4.shared.b16 {%0,%1,%2,%3}, [%4];"
        : "=r"(r[0]), "=r"(r[1]), "=r"(r[2]), "=r"(r[3]) : "r"(a));
}
__device__ __forceinline__ void ldsm4t(uint32_t (&r)[4], uint32_t a) {
    asm volatile("ldmatrix.sync.aligned.m8n8.x4.trans.shared.b16 {%0,%1,%2,%3}, [%4];"
        : "=r"(r[0]), "=r"(r[1]), "=r"(r[2]), "=r"(r[3]) : "r"(a));
}
__device__ __forceinline__ void ldsm2t(uint32_t (&r)[2], uint32_t a) {
    asm volatile("ldmatrix.sync.aligned.m8n8.x2.trans.shared.b16 {%0,%1}, [%2];"
        : "=r"(r[0]), "=r"(r[1]) : "r"(a));
}
__device__ __forceinline__ void ldsm2(uint32_t (&r)[2], uint32_t a) {
    asm volatile("ldmatrix.sync.aligned.m8n8.x2.shared.b16 {%0,%1}, [%2];"
        : "=r"(r[0]), "=r"(r[1]) : "r"(a));
}
__device__ __forceinline__ void mma16816(float (&d)[4], const uint32_t (&a)[4], const uint32_t (&b)[2]) {
    asm volatile("mma.sync.aligned.m16n8k16.row.col.f32.bf16.bf16.f32 "
        "{%0,%1,%2,%3}, {%4,%5,%6,%7}, {%8,%9}, {%0,%1,%2,%3};"
        : "+f"(d[0]), "+f"(d[1]), "+f"(d[2]), "+f"(d[3])
        : "r"(a[0]), "r"(a[1]), "r"(a[2]), "r"(a[3]), "r"(b[0]), "r"(b[1]));
}

// ============== 128x256 tile GEMM (main path) ==============
// per buffer: Ah 128x80B @0 | Al @10240 | Bh 32x528B @20480 | Bl @37376
#define W_OFF_AL 10240
#define W_OFF_BH 20480
#define W_OFF_BL 37376
#define W_BUFSZ  54272
#define SMEM_W   (3*W_BUFSZ)

// modes: 0 = C=acc; 1 = C+=acc; 2 = fused MoE up: B interleaves W1/W3 at 8-col
//        granularity (n0 is LOGICAL col base, 128 logical cols per CTA);
//        epilogue computes silu(u)*g in-register and writes bf16 hi/lo to Hh/Hl.
__device__ __forceinline__ void mma_block256(
    const bf16* __restrict__ Ah, const bf16* __restrict__ Al, int lda,
    const int* __restrict__ rows, int count, int m0,
    const bf16* __restrict__ Bh, const bf16* __restrict__ Bl,
    const bf16* __restrict__ B2h, const bf16* __restrict__ B2l, int ldb, int n0,
    int K, float* __restrict__ C, int ldc, int mode,
    bf16* __restrict__ Hh, bf16* __restrict__ Hl,
    char* dsm, uint32_t sb)
{
    const int tid = threadIdx.x, lane = tid & 31, wid = tid >> 5;
    const int wm = (wid & 1) * 64, wn = (wid >> 1) * 64;
    const int ar = tid >> 1, akc = (tid & 1) * 16;
    const int gm = m0 + ar;
    const bool av = gm < count;
    const bf16 *pAh = nullptr, *pAl = nullptr;
    if (av) {
        size_t rr = (size_t)(rows ? rows[gm] : gm) * lda + akc;
        pAh = Ah + rr; pAl = Al + rr;
    }
    const uint32_t ao = (uint32_t)ar * 80 + (uint32_t)akc * 2;

    if (!av) {
        uint4 z = make_uint4(0,0,0,0);
        #pragma unroll
        for (int s = 0; s < 3; s++) {
            char* bb = dsm + s * W_BUFSZ;
            *(uint4*)(bb + ao) = z;              *(uint4*)(bb + ao + 16) = z;
            *(uint4*)(bb + W_OFF_AL + ao) = z;   *(uint4*)(bb + W_OFF_AL + ao + 16) = z;
        }
    }

    float acc[4][8][4];
    #pragma unroll
    for (int a = 0; a < 4; a++)
        #pragma unroll
        for (int b = 0; b < 8; b++)
            #pragma unroll
            for (int c = 0; c < 4; c++) acc[a][b][c] = 0.f;

    auto ISSUE = [&](int k0, uint32_t sbuf) {
        if (av) {
            cpa(sbuf + ao,                 pAh + k0);
            cpa(sbuf + ao + 16,            pAh + k0 + 8);
            cpa(sbuf + W_OFF_AL + ao,      pAl + k0);
            cpa(sbuf + W_OFF_AL + ao + 16, pAl + k0 + 8);
        }
        #pragma unroll
        for (int j = 0; j < 4; j++) {
            int u = tid + j * 256;
            int row = u >> 5, c16 = u & 31;
            uint32_t doff = (uint32_t)row * 528 + (uint32_t)c16 * 16;
            if (mode == 2) {
                // interleaved: even c16 -> W1 cols, odd c16 -> W3 cols (same logical)
                int lcol = n0 + (c16 >> 1) * 8;
                const bf16* sh = ((c16 & 1) ? B2h : Bh) + (size_t)(k0 + row) * ldb + lcol;
                const bf16* sl = ((c16 & 1) ? B2l : Bl) + (size_t)(k0 + row) * ldb + lcol;
                cpa(sbuf + W_OFF_BH + doff, sh);
                cpa(sbuf + W_OFF_BL + doff, sl);
            } else {
                const bf16* sh = Bh + (size_t)(k0 + row) * ldb + n0 + c16 * 8;
                const bf16* sl = Bl + (size_t)(k0 + row) * ldb + n0 + c16 * 8;
                cpa(sbuf + W_OFF_BH + doff, sh);
                cpa(sbuf + W_OFF_BL + doff, sl);
            }
        }
    };

    auto COMPUTE = [&](uint32_t boff) {
        uint32_t abase = sb + boff + (uint32_t)(wm + (lane & 15)) * 80 + ((lane >> 4) * 16);
        uint32_t klocal = (uint32_t)((lane & 7) + ((lane >> 3) & 1) * 8);
        uint32_t bcol = (uint32_t)(wn + ((lane >> 4) & 1) * 8);
        #pragma unroll
        for (int ks = 0; ks < 2; ks++) {
            uint32_t ah4[4][4], al4[4][4];
            #pragma unroll
            for (int mt = 0; mt < 4; mt++) {
                uint32_t aa = abase + mt * (16 * 80) + ks * 32;
                ldsm4(ah4[mt], aa);
                ldsm4(al4[mt], aa + W_OFF_AL);
            }
            uint32_t bh[4][4], bl[4][4];
            uint32_t bkb = sb + boff + W_OFF_BH + (klocal + ks * 16) * 528 + bcol * 2;
            #pragma unroll
            for (int ng = 0; ng < 4; ng++) {
                uint32_t ba = bkb + ng * 32;   // 16 cols * 2B
                ldsm4t(bh[ng], ba);
                ldsm4t(bl[ng], ba + (W_OFF_BL - W_OFF_BH));
            }
            #pragma unroll
            for (int mt = 0; mt < 4; mt++)
                #pragma unroll
                for (int nt = 0; nt < 8; nt++) {
                    const int ng = nt >> 1, hf = (nt & 1) * 2;
                    uint32_t bhf[2] = { bh[ng][hf], bh[ng][hf + 1] };
                    uint32_t blf[2] = { bl[ng][hf], bl[ng][hf + 1] };
                    mma16816(acc[mt][nt], ah4[mt], bhf);
                    mma16816(acc[mt][nt], ah4[mt], blf);
                    mma16816(acc[mt][nt], al4[mt], bhf);
                }
        }
    };

    const int NC = K >> 5;
    ISSUE(0, sb); cp_commit();
    if (NC > 1) { ISSUE(32, sb + W_BUFSZ); cp_commit(); }
    for (int c = 0; c < NC; c++) {
        if (c == NC - 1) cp_wait0(); else cp_wait1();
        __syncthreads();
        COMPUTE((uint32_t)(c % 3) * W_BUFSZ);
        if (c + 2 < NC) { ISSUE((c + 2) << 5, sb + (uint32_t)((c + 2) % 3) * W_BUFSZ); cp_commit(); }
    }

    if (mode == 2) {
        // acc[mt][2s] = u, acc[mt][2s+1] = g for logical col L
        #pragma unroll
        for (int mt = 0; mt < 4; mt++) {
            int r0 = m0 + wm + mt * 16 + (lane >> 2);
            #pragma unroll
            for (int s = 0; s < 4; s++) {
                int L = n0 + (wn >> 1) + s * 8 + (lane & 3) * 2;
                float* du = acc[mt][2*s];
                float* dg = acc[mt][2*s + 1];
                #pragma unroll
                for (int hrow = 0; hrow < 2; hrow++) {
                    int r = r0 + hrow * 8;
                    if (r >= count) continue;
                    float u0 = du[hrow*2], u1 = du[hrow*2 + 1];
                    float g0 = dg[hrow*2], g1 = dg[hrow*2 + 1];
                    float h0 = (u0 / (1.f + expf(-u0))) * g0;
                    float h1 = (u1 / (1.f + expf(-u1))) * g1;
                    bf162 hh = __floats2bfloat162_rn(h0, h1);
                    bf162 ll = __floats2bfloat162_rn(h0 - __low2float(hh), h1 - __high2float(hh));
                    size_t o = (size_t)r * ldc + L;
                    *(bf162*)(Hh + o) = hh;
                    *(bf162*)(Hl + o) = ll;
                }
            }
        }
        return;
    }

    #pragma unroll
    for (int mt = 0; mt < 4; mt++) {
        int r0 = m0 + wm + mt * 16 + (lane >> 2);
        #pragma unroll
        for (int nt = 0; nt < 8; nt++) {
            int cc = n0 + wn + nt * 8 + (lane & 3) * 2;
            float* d = acc[mt][nt];
            #pragma unroll
            for (int hrow = 0; hrow < 2; hrow++) {
                int r = r0 + hrow * 8;
                if (r >= count) continue;
                float d0 = d[hrow*2], d1 = d[hrow*2 + 1];
                size_t o = (size_t)r * ldc + cc;
                if (mode == 0) {
                    *(float2*)(C + o) = make_float2(d0, d1);
                } else {
                    float2 p = *(const float2*)(C + o);
                    *(float2*)(C + o) = make_float2(p.x + d0, p.y + d1);
                }
            }
        }
    }
}

// dense GEMM: grid (M/128, N/256)
__global__ __launch_bounds__(256, 1) void k_mma256(
    const bf16* __restrict__ Ah, const bf16* __restrict__ Al,
    const bf16* __restrict__ Bh, const bf16* __restrict__ Bl,
    float* __restrict__ C, int K, int ldb, int ldc, int mode)
{
    extern __shared__ __align__(16) char dsm[];
    mma_block256(Ah, Al, K, nullptr, 1 << 30, blockIdx.x * 128,
                 Bh, Bl, nullptr, nullptr, ldb, blockIdx.y * 256,
                 K, C, ldc, mode, nullptr, nullptr, dsm, smem_u32(dsm));
}

// MoE: which 1 = fused up (X W1, X W3, silu in-register) -> hidden split; 2 = H W2 -> g_yb
__global__ __launch_bounds__(256, 1) void k_moe_mma(
    const bf16* __restrict__ Wh, const bf16* __restrict__ Wl,
    const bf16* __restrict__ W3h, const bf16* __restrict__ W3l, int which)
{
    int e = blockIdx.z;
    int count = g_cnt[e];
    int m0 = blockIdx.x * 128;
    if (m0 >= count) return;
    extern __shared__ __align__(16) char dsm[];
    uint32_t sb = smem_u32(dsm);
    if (which == 1) {
        int n0 = blockIdx.y * 128;   // logical cols
        mma_block256(g_ah, g_al, D_, g_rows + e * T_, count, m0,
                     Wh + (size_t)e * D_ * F_, Wl + (size_t)e * D_ * F_,
                     W3h + (size_t)e * D_ * F_, W3l + (size_t)e * D_ * F_, F_, n0,
                     D_, nullptr, F_, 2,
                     g_hbh + (size_t)e * T_ * F_, g_hbl + (size_t)e * T_ * F_, dsm, sb);
    } else {
        int n0 = blockIdx.y * 256;
        mma_block256(g_hbh + (size_t)e * T_ * F_, g_hbl + (size_t)e * T_ * F_, F_, nullptr, count, m0,
                     Wh + (size_t)e * F_ * D_, Wl + (size_t)e * F_ * D_, nullptr, nullptr, D_, n0,
                     F_, g_yb + (size_t)e * T_ * D_, D_, 0, nullptr, nullptr, dsm, sb);
    }
}

// ============== 128x128 tile path (k_avm only, nlim=64) ==============
#define OFF_AL 10240
#define OFF_BH 20480
#define OFF_BL 29184
#define BUFSZ  37888
#define SMEM_MMA128 (3*BUFSZ)

// mode 0: fp32 C; mode 3: split-store bf16 hi/lo to Hh/Hl
__device__ __forceinline__ void mma_block128(
    const bf16* __restrict__ Ah, const bf16* __restrict__ Al, int lda,
    int count, int m0,
    const bf16* __restrict__ Bh, const bf16* __restrict__ Bl, int ldb, int n0, int nlim,
    int K, float* __restrict__ C, bf16* __restrict__ Hh, bf16* __restrict__ Hl, int ldc,
    int mode, char* dsm, uint32_t sb)
{
    const int tid = threadIdx.x, lane = tid & 31, wid = tid >> 5;
    const int wm = (wid & 1) * 64, wn = (wid >> 1) * 32;
    const int ar = tid >> 1, akc = (tid & 1) * 16;
    const int bkr = tid >> 3, bn16 = (tid & 7) * 16;
    const int gm = m0 + ar;
    const bool av = gm < count;
    const bf16 *pAh = nullptr, *pAl = nullptr;
    if (av) {
        size_t rr = (size_t)gm * lda + akc;
        pAh = Ah + rr; pAl = Al + rr;
    }
    const int bcol = (nlim < 128) ? (bn16 & (nlim - 1)) : bn16;
    const bf16* pBh = Bh + (size_t)bkr * ldb + n0 + bcol;
    const bf16* pBl = Bl + (size_t)bkr * ldb + n0 + bcol;
    const uint32_t ao = (uint32_t)ar * 80 + (uint32_t)akc * 2;
    const uint32_t bo = (uint32_t)OFF_BH + (uint32_t)bkr * 272 + (uint32_t)bn16 * 2;

    if (!av) {
        uint4 z = make_uint4(0,0,0,0);
        #pragma unroll
        for (int s = 0; s < 3; s++) {
            char* bb = dsm + s * BUFSZ;
            *(uint4*)(bb + ao) = z;            *(uint4*)(bb + ao + 16) = z;
            *(uint4*)(bb + OFF_AL + ao) = z;   *(uint4*)(bb + OFF_AL + ao + 16) = z;
        }
    }

    float acc[4][4][4];
    #pragma unroll
    for (int a = 0; a < 4; a++)
        #pragma unroll
        for (int b = 0; b < 4; b++)
            #pragma unroll
            for (int c = 0; c < 4; c++) acc[a][b][c] = 0.f;

    auto ISSUE = [&](int k0, uint32_t sbuf) {
        if (av) {
            cpa(sbuf + ao,               pAh + k0);
            cpa(sbuf + ao + 16,          pAh + k0 + 8);
            cpa(sbuf + OFF_AL + ao,      pAl + k0);
            cpa(sbuf + OFF_AL + ao + 16, pAl + k0 + 8);
        }
        const bf16* b = pBh + (size_t)k0 * ldb;
        cpa(sbuf + bo,      b);
        cpa(sbuf + bo + 16, b + 8);
        b = pBl + (size_t)k0 * ldb;
        cpa(sbuf + (OFF_BL - OFF_BH) + bo,      b);
        cpa(sbuf + (OFF_BL - OFF_BH) + bo + 16, b + 8);
    };

    auto COMPUTE = [&](uint32_t boff) {
        uint32_t abase = sb + boff + (uint32_t)(wm + (lane & 15)) * 80 + ((lane >> 4) * 8) * 2;
        uint32_t bbase = sb + boff + OFF_BH
                       + (uint32_t)((lane & 7) + ((lane >> 3) & 1) * 8) * 272
                       + (uint32_t)wn * 2;
        #pragma unroll
        for (int ks = 0; ks < 2; ks++) {
            uint32_t ah4[4][4], al4[4][4], bh2[4][2], bl2[4][2];
            #pragma unroll
            for (int mt = 0; mt < 4; mt++) {
                uint32_t aa = abase + mt * (16 * 80) + ks * 32;
                ldsm4(ah4[mt], aa);
                ldsm4(al4[mt], aa + OFF_AL);
            }
            #pragma unroll
            for (int nt = 0; nt < 4; nt++) {
                uint32_t ba = bbase + ks * (16 * 272) + nt * 16;
                ldsm2t(bh2[nt], ba);
                ldsm2t(bl2[nt], ba + (OFF_BL - OFF_BH));
            }
            #pragma unroll
            for (int mt = 0; mt < 4; mt++)
                #pragma unroll
                for (int nt = 0; nt < 4; nt++) {
                    mma16816(acc[mt][nt], ah4[mt], bh2[nt]);
                    mma16816(acc[mt][nt], ah4[mt], bl2[nt]);
                    mma16816(acc[mt][nt], al4[mt], bh2[nt]);
                }
        }
    };

    const int NC = K >> 5;
    ISSUE(0, sb); cp_commit();
    if (NC > 1) { ISSUE(32, sb + BUFSZ); cp_commit(); }
    for (int c = 0; c < NC; c++) {
        if (c == NC - 1) cp_wait0(); else cp_wait1();
        __syncthreads();
        COMPUTE((uint32_t)(c % 3) * BUFSZ);
        if (c + 2 < NC) { ISSUE((c + 2) << 5, sb + (uint32_t)((c + 2) % 3) * BUFSZ); cp_commit(); }
    }

    #pragma unroll
    for (int mt = 0; mt < 4; mt++) {
        int r0 = m0 + wm + mt * 16 + (lane >> 2);
        #pragma unroll
        for (int nt = 0; nt < 4; nt++) {
            int ln = wn + nt * 8 + (lane & 3) * 2;
            if (ln >= nlim) continue;
            int cc = n0 + ln;
            float* d = acc[mt][nt];
            #pragma unroll
            for (int hrow = 0; hrow < 2; hrow++) {
                int r = r0 + hrow * 8;
                if (r >= count) continue;
                float d0 = d[hrow*2], d1 = d[hrow*2 + 1];
                size_t o = (size_t)r * ldc + cc;
                if (mode == 0) {
                    *(float2*)(C + o) = make_float2(d0, d1);
                } else {
                    bf162 hh = __floats2bfloat162_rn(d0, d1);
                    bf162 ll = __floats2bfloat162_rn(d0 - __low2float(hh), d1 - __high2float(hh));
                    *(bf162*)(Hh + o) = hh;
                    *(bf162*)(Hl + o) = ll;
                }
            }
        }
    }
}

// O = P V: grid (4, 1, 64); writes bf16 hi/lo DIRECTLY into g_ah/g_al (xn split is dead by now)
__global__ __launch_bounds__(256, 1) void k_avm()
{
    int b = blockIdx.z, chunk = b >> 4, head = b & 15, kvh = head >> 2;
    int m0 = blockIdx.x * 128;
    extern __shared__ __align__(16) char dsm[];
    size_t obase = (size_t)chunk * CH * D_ + head * 64;
    mma_block128(g_hbh + (size_t)b * CH * CH, g_hbl + (size_t)b * CH * CH, CH, CH, m0,
                 g_qkvh + (size_t)chunk * CH * QKV_ + 1280 + kvh * 64,
                 g_qkvl + (size_t)chunk * CH * QKV_ + 1280 + kvh * 64, QKV_, 0, 64,
                 m0 + 128, nullptr, g_ah + obase, g_al + obase, D_, 3, dsm, smem_u32(dsm));
}

// ---------------- scores S = Q K^T: grid (4, 4, 64); skips n0>m0 tiles + masked warp-tiles ----------------
#define QK_AL 10240
#define QK_KH 20480
#define QK_KL 30720
#define QK_BUF 40960
#define SMEM_QK (2*QK_BUF)

__global__ __launch_bounds__(256, 1) void k_qk()
{
    if (blockIdx.y > blockIdx.x) return;
    extern __shared__ __align__(16) char dsm[];
    uint32_t sb = smem_u32(dsm);
    int b = blockIdx.z, chunk = b >> 4, head = b & 15, kvh = head >> 2;
    int m0 = blockIdx.x * 128, n0 = blockIdx.y * 128;
    int tid = threadIdx.x, lane = tid & 31, wid = tid >> 5;
    int wm = (wid & 1) * 64, wn = (wid >> 1) * 32;
    int ar = tid >> 1, akc = (tid & 1) * 16;
    const bf16* pQh = g_qkvh + (size_t)(chunk*CH + m0 + ar) * QKV_ + head * 64 + akc;
    const bf16* pQl = g_qkvl + (size_t)(chunk*CH + m0 + ar) * QKV_ + head * 64 + akc;
    const bf16* pKh = g_qkvh + (size_t)(chunk*CH + n0 + ar) * QKV_ + 1024 + kvh * 64 + akc;
    const bf16* pKl = g_qkvl + (size_t)(chunk*CH + n0 + ar) * QKV_ + 1024 + kvh * 64 + akc;
    const uint32_t ao = (uint32_t)ar * 80 + (uint32_t)akc * 2;

    float acc[4][4][4];
    #pragma unroll
    for (int a = 0; a < 4; a++)
        #pragma unroll
        for (int bb = 0; bb < 4; bb++)
            #pragma unroll
            for (int c = 0; c < 4; c++) acc[a][bb][c] = 0.f;

    auto ISSUE = [&](int k0, uint32_t sbuf) {
        cpa(sbuf + ao,               pQh + k0); cpa(sbuf + ao + 16,           pQh + k0 + 8);
        cpa(sbuf + QK_AL + ao,       pQl + k0); cpa(sbuf + QK_AL + ao + 16,   pQl + k0 + 8);
        cpa(sbuf + QK_KH + ao,       pKh + k0); cpa(sbuf + QK_KH + ao + 16,   pKh + k0 + 8);
        cpa(sbuf + QK_KL + ao,       pKl + k0); cpa(sbuf + QK_KL + ao + 16,   pKl + k0 + 8);
    };
    auto COMPUTE = [&](uint32_t boff) {
        uint32_t abase = sb + boff + (uint32_t)(wm + (lane & 15)) * 80 + ((lane >> 4) * 8) * 2;
        #pragma unroll
        for (int ks = 0; ks < 2; ks++) {
            uint32_t ah4[4][4], al4[4][4], bh2[4][2], bl2[4][2];
            #pragma unroll
            for (int mt = 0; mt < 4; mt++) {
                uint32_t aa = abase + mt * (16 * 80) + ks * 32;
                ldsm4(ah4[mt], aa);
                ldsm4(al4[mt], aa + QK_AL);
            }
            #pragma unroll
            for (int nt = 0; nt < 4; nt++) {
                if (n0 + wn + nt * 8 > m0 + wm + 63) continue;   // fully causal-masked sub-tile
                uint32_t ba = sb + boff + QK_KH
                            + (uint32_t)(wn + nt * 8 + (lane & 7)) * 80
                            + ks * 32 + ((lane >> 3) & 1) * 16;
                ldsm2(bh2[nt], ba);
                ldsm2(bl2[nt], ba + (QK_KL - QK_KH));
                #pragma unroll
                for (int mt = 0; mt < 4; mt++) {
                    mma16816(acc[mt][nt], ah4[mt], bh2[nt]);
                    mma16816(acc[mt][nt], ah4[mt], bl2[nt]);
                    mma16816(acc[mt][nt], al4[mt], bh2[nt]);
                }
            }
        }
    };

    ISSUE(0, sb); cp_commit();
    ISSUE(32, sb + QK_BUF); cp_commit();
    cp_wait1(); __syncthreads(); COMPUTE(0);
    cp_wait0(); __syncthreads(); COMPUTE(QK_BUF);

    float* S = g_sc + (size_t)b * CH * CH;
    #pragma unroll
    for (int mt = 0; mt < 4; mt++) {
        int r0 = wm + mt * 16 + (lane >> 2);
        #pragma unroll
        for (int nt = 0; nt < 4; nt++) {
            int c0 = wn + nt * 8 + (lane & 3) * 2;
            float* d = acc[mt][nt];
            #pragma unroll
            for (int hrow = 0; hrow < 2; hrow++) {
                int qg = m0 + r0 + hrow * 8;
                int kg = n0 + c0;
                float v0 = d[hrow*2] * 0.125f, v1 = d[hrow*2 + 1] * 0.125f;
                if (kg > qg)     v0 = -1e30f;
                if (kg + 1 > qg) v1 = -1e30f;
                *(float2*)(S + (size_t)qg * CH + kg) = make_float2(v0, v1);
            }
        }
    }
}

// ---- split helpers ----
__device__ __forceinline__ void split8_body(const float* __restrict__ x,
    bf16* __restrict__ hh, bf16* __restrict__ ll, size_t i) {
    const float4* xv = (const float4*)x;
    float4 a = xv[2*i], b = xv[2*i+1];
    bf162 h0 = __floats2bfloat162_rn(a.x, a.y);
    bf162 h1 = __floats2bfloat162_rn(a.z, a.w);
    bf162 h2 = __floats2bfloat162_rn(b.x, b.y);
    bf162 h3 = __floats2bfloat162_rn(b.z, b.w);
    bf162 l0 = __floats2bfloat162_rn(a.x - __low2float(h0), a.y - __high2float(h0));
    bf162 l1 = __floats2bfloat162_rn(a.z - __low2float(h1), a.w - __high2float(h1));
    bf162 l2 = __floats2bfloat162_rn(b.x - __low2float(h2), b.y - __high2float(h2));
    bf162 l3 = __floats2bfloat162_rn(b.z - __low2float(h3), b.w - __high2float(h3));
    ((uint4*)hh)[i] = make_uint4(*(uint32_t*)&h0, *(uint32_t*)&h1, *(uint32_t*)&h2, *(uint32_t*)&h3);
    ((uint4*)ll)[i] = make_uint4(*(uint32_t*)&l0, *(uint32_t*)&l1, *(uint32_t*)&l2, *(uint32_t*)&l3);
}

// qkv weight segments: grid (1024, 6)
__global__ void k_convqkv(const float* __restrict__ wq, const float* __restrict__ wk,
                          const float* __restrict__ wv) {
    int seg = blockIdx.y, l = seg / 3, which = seg - l * 3;
    const float* src; int N; size_t doff;
    if (which == 0)      { src = wq + (size_t)l*D_*1024; N = 1024; doff = (size_t)l*D_*QKV_; }
    else if (which == 1) { src = wk + (size_t)l*D_*256;  N = 256;  doff = (size_t)l*D_*QKV_ + 1024; }
    else                 { src = wv + (size_t)l*D_*256;  N = 256;  doff = (size_t)l*D_*QKV_ + 1280; }
    size_t i = (size_t)blockIdx.x * 256 + threadIdx.x;
    size_t e = i * 4;
    if (e >= (size_t)D_ * N) return;
    int r = (int)(e / N), c = (int)(e % N);
    float4 v = *(const float4*)(src + e);
    size_t o = doff + (size_t)r * QKV_ + c;
    bf162 h0 = __floats2bfloat162_rn(v.x, v.y);
    bf162 l0 = __floats2bfloat162_rn(v.x - __low2float(h0), v.y - __high2float(h0));
    bf162 h1 = __floats2bfloat162_rn(v.z, v.w);
    bf162 l1 = __floats2bfloat162_rn(v.z - __low2float(h1), v.w - __high2float(h1));
    *(bf162*)(c_qkvh+o) = h0; *(bf162*)(c_qkvh+o+2) = h1;
    *(bf162*)(c_qkvl+o) = l0; *(bf162*)(c_qkvl+o+2) = l1;
}

// wo/w1/w3/w2/lm: grid-stride, streaming loads/stores, 16 floats/thread
__global__ void k_convw5(const float* __restrict__ wo, const float* __restrict__ w1,
                         const float* __restrict__ w3, const float* __restrict__ w2,
                         const float* __restrict__ lm) {
    int y = blockIdx.y;
    const float* src; bf16 *dh, *dl; size_t n;
    if (y == 0)      { src = wo; dh = c_woh; dl = c_wol; n = (size_t)NL*D_*D_; }
    else if (y == 1) { src = w1; dh = c_w1h; dl = c_w1l; n = (size_t)NL*NE*D_*F_; }
    else if (y == 2) { src = w3; dh = c_w3h; dl = c_w3l; n = (size_t)NL*NE*D_*F_; }
    else if (y == 3) { src = w2; dh = c_w2h; dl = c_w2l; n = (size_t)NL*NE*F_*D_; }
    else             { src = lm; dh = c_lmh; dl = c_lml; n = (size_t)D_*NV; }
    size_t nchunks = n >> 4;
    size_t stride = (size_t)gridDim.x * 256;
    const float4* xv = (const float4*)src;
    for (size_t i = (size_t)blockIdx.x * 256 + threadIdx.x; i < nchunks; i += stride) {
        float4 a = __ldcs(xv + 4*i);
        float4 b = __ldcs(xv + 4*i + 1);
        float4 c = __ldcs(xv + 4*i + 2);
        float4 d = __ldcs(xv + 4*i + 3);
        bf162 h0 = __floats2bfloat162_rn(a.x, a.y), h1 = __floats2bfloat162_rn(a.z, a.w);
        bf162 h2 = __floats2bfloat162_rn(b.x, b.y), h3 = __floats2bfloat162_rn(b.z, b.w);
        bf162 h4 = __floats2bfloat162_rn(c.x, c.y), h5 = __floats2bfloat162_rn(c.z, c.w);
        bf162 h6 = __floats2bfloat162_rn(d.x, d.y), h7 = __floats2bfloat162_rn(d.z, d.w);
        bf162 l0 = __floats2bfloat162_rn(a.x - __low2float(h0), a.y - __high2float(h0));
        bf162 l1 = __floats2bfloat162_rn(a.z - __low2float(h1), a.w - __high2float(h1));
        bf162 l2 = __floats2bfloat162_rn(b.x - __low2float(h2), b.y - __high2float(h2));
        bf162 l3 = __floats2bfloat162_rn(b.z - __low2float(h3), b.w - __high2float(h3));
        bf162 l4 = __floats2bfloat162_rn(c.x - __low2float(h4), c.y - __high2float(h4));
        bf162 l5 = __floats2bfloat162_rn(c.z - __low2float(h5), c.w - __high2float(h5));
        bf162 l6 = __floats2bfloat162_rn(d.x - __low2float(h6), d.y - __high2float(h6));
        bf162 l7 = __floats2bfloat162_rn(d.z - __low2float(h7), d.w - __high2float(h7));
        __stcs((uint4*)dh + 2*i,     make_uint4(*(uint32_t*)&h0, *(uint32_t*)&h1, *(uint32_t*)&h2, *(uint32_t*)&h3));
        __stcs((uint4*)dh + 2*i + 1, make_uint4(*(uint32_t*)&h4, *(uint32_t*)&h5, *(uint32_t*)&h6, *(uint32_t*)&h7));
        __stcs((uint4*)dl + 2*i,     make_uint4(*(uint32_t*)&l0, *(uint32_t*)&l1, *(uint32_t*)&l2, *(uint32_t*)&l3));
        __stcs((uint4*)dl + 2*i + 1, make_uint4(*(uint32_t*)&l4, *(uint32_t*)&l5, *(uint32_t*)&l6, *(uint32_t*)&l7));
    }
}

// ---------------- fused rms + split ----------------
__global__ void k_rmssplit(const float* __restrict__ x, const float* __restrict__ w,
                           float* __restrict__ out, bf16* __restrict__ hh, bf16* __restrict__ ll) {
    int t = blockIdx.x, tid = threadIdx.x;
    __shared__ float sh[256];
    float4 v = ((const float4*)(x + (size_t)t*D_))[tid];
    float s = v.x*v.x + v.y*v.y + v.z*v.z + v.w*v.w;
    sh[tid] = s; __syncthreads();
    for (int o = 128; o > 0; o >>= 1) { if (tid < o) sh[tid] += sh[tid+o]; __syncthreads(); }
    float scale = rsqrtf(sh[0] / (float)D_ + 1e-6f);
    float4 wv = ((const float4*)w)[tid];
    float4 o;
    o.x = wv.x * v.x * scale; o.y = wv.y * v.y * scale;
    o.z = wv.z * v.z * scale; o.w = wv.w * v.w * scale;
    ((float4*)(out + (size_t)t*D_))[tid] = o;
    bf162 h0 = __floats2bfloat162_rn(o.x, o.y);
    bf162 h1 = __floats2bfloat162_rn(o.z, o.w);
    bf162 l0 = __floats2bfloat162_rn(o.x - __low2float(h0), o.y - __high2float(h0));
    bf162 l1 = __floats2bfloat162_rn(o.z - __low2float(h1), o.w - __high2float(h1));
    ((uint2*)(hh + (size_t)t*D_))[tid] = make_uint2(*(uint32_t*)&h0, *(uint32_t*)&h1);
    ((uint2*)(ll + (size_t)t*D_))[tid] = make_uint2(*(uint32_t*)&l0, *(uint32_t*)&l1);
}

// ---------------- fused rope + qkv split: grid T_, 192 threads ----------------
__global__ void k_ropesplit() {
    int t = blockIdx.x, tid = threadIdx.x;
    int c0 = tid * 8;
    float p = (float)(t & (CH-1));
    const float* base = g_qkv + (size_t)t * QKV_;
    float4 a = *(const float4*)(base + c0);
    float4 b = *(const float4*)(base + c0 + 4);
    float vv[8] = {a.x, a.y, a.z, a.w, b.x, b.y, b.z, b.w};
    if (c0 < 1280) {
        #pragma unroll
        for (int j = 0; j < 4; j++) {
            int c = c0 + 2*j;
            int i = (c & 63) >> 1;
            float ang = p * powf(1000000.0f, -(float)i/32.0f);
            float cs = cosf(ang), sn = sinf(ang);
            float x1 = vv[2*j], x2 = vv[2*j+1];
            vv[2*j]   = x1*cs - x2*sn;
            vv[2*j+1] = x1*sn + x2*cs;
        }
    }
    bf162 h[4], l[4];
    #pragma unroll
    for (int j = 0; j < 4; j++) {
        h[j] = __floats2bfloat162_rn(vv[2*j], vv[2*j+1]);
        l[j] = __floats2bfloat162_rn(vv[2*j] - __low2float(h[j]), vv[2*j+1] - __high2float(h[j]));
    }
    size_t o = ((size_t)t * QKV_ + c0) >> 3;
    ((uint4*)g_qkvh)[o] = make_uint4(*(uint32_t*)&h[0], *(uint32_t*)&h[1], *(uint32_t*)&h[2], *(uint32_t*)&h[3]);
    ((uint4*)g_qkvl)[o] = make_uint4(*(uint32_t*)&l[0], *(uint32_t*)&l[1], *(uint32_t*)&l[2], *(uint32_t*)&l[3]);
}

// ---------------- misc kernels ----------------
__global__ void k_embed(const int* __restrict__ ids, const float* __restrict__ ew) {
    int t = blockIdx.x;
    if (t == 0 && threadIdx.x == 0) g_aux[0] = 0.f;
    size_t r = (size_t)ids[t] * D_;
    for (int d = threadIdx.x; d < D_; d += blockDim.x) g_h[(size_t)t*D_ + d] = ew[r + d];
}
// warp-per-row softmax: reads fp32 S, writes P as bf16 hi/lo
__global__ void k_softmax() {
    int tid = threadIdx.x, lane = tid & 31, w = tid >> 5;
    int row = blockIdx.x * 8 + w;
    int q = row & (CH-1);
    const float* r = g_sc + (size_t)row * CH;
    float x[16];
    float mx = -1e30f;
    #pragma unroll
    for (int j = 0; j < 4; j++) {
        int c = j * 128 + lane * 4;
        float4 v = *(const float4*)(r + c);
        x[4*j]   = (c   <= q) ? v.x : -1e30f;
        x[4*j+1] = (c+1 <= q) ? v.y : -1e30f;
        x[4*j+2] = (c+2 <= q) ? v.z : -1e30f;
        x[4*j+3] = (c+3 <= q) ? v.w : -1e30f;
        mx = fmaxf(mx, fmaxf(fmaxf(x[4*j], x[4*j+1]), fmaxf(x[4*j+2], x[4*j+3])));
    }
    #pragma unroll
    for (int o = 16; o > 0; o >>= 1) mx = fmaxf(mx, __shfl_xor_sync(0xffffffffu, mx, o));
    float sum = 0.f;
    #pragma unroll
    for (int j = 0; j < 16; j++) { x[j] = (x[j] > -1e29f) ? expf(x[j] - mx) : 0.f; sum += x[j]; }
    #pragma unroll
    for (int o = 16; o > 0; o >>= 1) sum += __shfl_xor_sync(0xffffffffu, sum, o);
    float inv = 1.f / sum;
    #pragma unroll
    for (int j = 0; j < 4; j++) {
        int c = j * 128 + lane * 4;
        float p0 = x[4*j]*inv, p1 = x[4*j+1]*inv, p2 = x[4*j+2]*inv, p3 = x[4*j+3]*inv;
        bf162 h0 = __floats2bfloat162_rn(p0, p1);
        bf162 h1 = __floats2bfloat162_rn(p2, p3);
        bf162 l0 = __floats2bfloat162_rn(p0 - __low2float(h0), p1 - __high2float(h0));
        bf162 l1 = __floats2bfloat162_rn(p2 - __low2float(h1), p3 - __high2float(h1));
        size_t o = ((size_t)row * CH + c) >> 2;
        ((uint2*)g_hbh)[o] = make_uint2(*(uint32_t*)&h0, *(uint32_t*)&h1);
        ((uint2*)g_hbl)[o] = make_uint2(*(uint32_t*)&l0, *(uint32_t*)&l1);
    }
}
__global__ void k_router(const float* __restrict__ rw) {
    int tid = threadIdx.x, lane = tid & 31, w = tid >> 5;
    int t = blockIdx.x*8 + w;
    const float* xr = g_xn + (size_t)t*D_;
    float acc[NE] = {};
    for (int dd = 0; dd < 32; dd++) {
        int d = dd*32 + lane;
        float x = xr[d];
        const float* rr = rw + (size_t)d*NE;
        #pragma unroll
        for (int e = 0; e < NE; e++) acc[e] += x * rr[e];
    }
    #pragma unroll
    for (int e = 0; e < NE; e++)
        for (int o = 16; o > 0; o >>= 1) acc[e] += __shfl_down_sync(0xffffffffu, acc[e], o);
    if (lane == 0) {
        float m = acc[0];
        #pragma unroll
        for (int e = 1; e < NE; e++) m = fmaxf(m, acc[e]);
        float p[NE], s = 0.f;
        #pragma unroll
        for (int e = 0; e < NE; e++) { p[e] = expf(acc[e]-m); s += p[e]; }
        float inv = 1.f/s;
        #pragma unroll
        for (int e = 0; e < NE; e++) { p[e] *= inv; g_probs[(size_t)t*NE + e] = p[e]; }
        int i0 = 0;
        #pragma unroll
        for (int e = 1; e < NE; e++) if (p[e] > p[i0]) i0 = e;
        int i1 = (i0 == 0) ? 1 : 0;
        #pragma unroll
        for (int e = 0; e < NE; e++) if (e != i0 && p[e] > p[i1]) i1 = e;
        float ws = p[i0] + p[i1];
        g_ti[2*t] = i0; g_ti[2*t+1] = i1;
        g_tw[2*t] = p[i0]/ws; g_tw[2*t+1] = p[i1]/ws;
    }
}
__global__ void k_aux() {
    int tid = threadIdx.x;
    if (tid < NE) g_cnt[tid] = 0;
    __shared__ float sh[256];
    __shared__ float totp[NE], totc[NE];
    float ps[NE] = {}, cs[NE] = {};
    for (int t = tid; t < T_; t += 256) {
        cs[g_ti[2*t]] += 1.f;
        #pragma unroll
        for (int e = 0; e < NE; e++) ps[e] += g_probs[(size_t)t*NE + e];
    }
    for (int e = 0; e < NE; e++) {
        sh[tid] = ps[e]; __syncthreads();
        for (int o = 128; o > 0; o >>= 1) { if (tid < o) sh[tid] += sh[tid+o]; __syncthreads(); }
        if (tid == 0) totp[e] = sh[0];
        __syncthreads();
        sh[tid] = cs[e]; __syncthreads();
        for (int o = 128; o > 0; o >>= 1) { if (tid < o) sh[tid] += sh[tid+o]; __syncthreads(); }
        if (tid == 0) totc[e] = sh[0];
        __syncthreads();
    }
    if (tid == 0) {
        float a = 0.f;
        for (int e = 0; e < NE; e++) a += (totc[e]/(float)T_) * (totp[e]/(float)T_);
        g_aux[0] += (float)NE * a;
    }
}
__global__ void k_bucket() {
    int t = blockIdx.x*256 + threadIdx.x;
    if (t >= T_) return;
    for (int j = 0; j < 2; j++) {
        int e = g_ti[2*t + j];
        int pos = atomicAdd(&g_cnt[e], 1);
        g_rows[e*T_ + pos] = t;
        g_slot[2*t + j] = e*T_ + pos;
    }
}
__global__ void k_combine() {
    int t = blockIdx.x, tid = threadIdx.x;
    int s0 = g_slot[2*t], s1 = g_slot[2*t+1];
    float w0 = g_tw[2*t], w1 = g_tw[2*t+1];
    const float* y0 = g_yb + (size_t)s0*D_;
    const float* y1 = g_yb + (size_t)s1*D_;
    float* hr = g_h + (size_t)t*D_;
    for (int d = tid; d < D_; d += 256) hr[d] += w0*y0[d] + w1*y1[d];
}
__global__ void k_task(const float* __restrict__ tw, const float* __restrict__ tb, float* __restrict__ out) {
    int c = blockIdx.x, tid = threadIdx.x;
    __shared__ float sh[256];
    float s = 0.f;
    for (int d = tid; d < D_; d += 256) s += g_xn[d] * tw[(size_t)d*16 + c];
    sh[tid] = s; __syncthreads();
    for (int o = 128; o > 0; o >>= 1) { if (tid < o) sh[tid] += sh[tid+o]; __syncthreads(); }
    if (tid == 0) out[OUT_TASK + c] = sh[0] + tb[c];
}
__global__ void k_mean1() {
    int b = blockIdx.x, tid = threadIdx.x;
    const float* x = g_xn + (size_t)b*128*D_ + tid*4;
    float4 a = make_float4(0.f,0.f,0.f,0.f);
    for (int r = 0; r < 128; r++) {
        float4 v = *(const float4*)(x + (size_t)r*D_);
        a.x += v.x; a.y += v.y; a.z += v.z; a.w += v.w;
    }
    *(float4*)(g_mp + b*D_ + tid*4) = a;
}
__global__ void k_mean2() {
    int d = blockIdx.x*256 + threadIdx.x;
    float s = 0.f;
    for (int b = 0; b < 16; b++) s += g_mp[b*D_ + d];
    g_xm[d] = s / (float)T_;
}
__global__ void k_eval(const float* __restrict__ ew, const float* __restrict__ eb, float* __restrict__ out) {
    int c = blockIdx.x, tid = threadIdx.x;
    __shared__ float sh[256];
    float s = 0.f;
    for (int d = tid; d < D_; d += 256) s += g_xm[d] * ew[(size_t)d*8 + c];
    sh[tid] = s; __syncthreads();
    for (int o = 128; o > 0; o >>= 1) { if (tid < o) sh[tid] += sh[tid+o]; __syncthreads(); }
    if (tid == 0) out[OUT_EVAL + c] = sh[0] + eb[c];
}
__global__ void k_auxw(float* __restrict__ out) { out[OUT_AUX] = g_aux[0]; }

// ---------------- launch ----------------
extern "C" void kernel_launch(void* const* d_in, const int* in_sizes, int n_in,
                              void* d_out, int out_size) {
    const int*   ids     = (const int*)  d_in[0];
    const float* embed_W = (const float*)d_in[1];
    const float* n1      = (const float*)d_in[2];
    const float* n2      = (const float*)d_in[3];
    const float* wq      = (const float*)d_in[4];
    const float* wk      = (const float*)d_in[5];
    const float* wv      = (const float*)d_in[6];
    const float* wo      = (const float*)d_in[7];
    const float* rw      = (const float*)d_in[8];
    const float* w1      = (const float*)d_in[9];
    const float* w3      = (const float*)d_in[10];
    const float* w2      = (const float*)d_in[11];
    const float* normf   = (const float*)d_in[12];
    const float* lm      = (const float*)d_in[13];
    const float* tw      = (const float*)d_in[14];
    const float* tb      = (const float*)d_in[15];
    const float* ew      = (const float*)d_in[16];
    const float* eb      = (const float*)d_in[17];
    float* out = (float*)d_out;

    float *p_h, *p_xn, *p_qkv;
    bf16 *p_ah, *p_al;
    bf16 *p_cqh, *p_cql, *p_cwoh, *p_cwol, *p_c1h, *p_c1l, *p_c3h, *p_c3l, *p_c2h, *p_c2l, *p_clh, *p_cll;
    cudaGetSymbolAddress((void**)&p_h,    g_h);
    cudaGetSymbolAddress((void**)&p_xn,   g_xn);
    cudaGetSymbolAddress((void**)&p_qkv,  g_qkv);
    cudaGetSymbolAddress((void**)&p_ah,   g_ah);
    cudaGetSymbolAddress((void**)&p_al,   g_al);
    cudaGetSymbolAddress((void**)&p_cqh,  c_qkvh);
    cudaGetSymbolAddress((void**)&p_cql,  c_qkvl);
    cudaGetSymbolAddress((void**)&p_cwoh, c_woh);
    cudaGetSymbolAddress((void**)&p_cwol, c_wol);
    cudaGetSymbolAddress((void**)&p_c1h,  c_w1h);
    cudaGetSymbolAddress((void**)&p_c1l,  c_w1l);
    cudaGetSymbolAddress((void**)&p_c3h,  c_w3h);
    cudaGetSymbolAddress((void**)&p_c3l,  c_w3l);
    cudaGetSymbolAddress((void**)&p_c2h,  c_w2h);
    cudaGetSymbolAddress((void**)&p_c2l,  c_w2l);
    cudaGetSymbolAddress((void**)&p_clh,  c_lmh);
    cudaGetSymbolAddress((void**)&p_cll,  c_lml);

    cudaFuncSetAttribute(k_mma256,  cudaFuncAttributeMaxDynamicSharedMemorySize, SMEM_W);
    cudaFuncSetAttribute(k_moe_mma, cudaFuncAttributeMaxDynamicSharedMemorySize, SMEM_W);
    cudaFuncSetAttribute(k_avm,     cudaFuncAttributeMaxDynamicSharedMemorySize, SMEM_MMA128);
    cudaFuncSetAttribute(k_qk,      cudaFuncAttributeMaxDynamicSharedMemorySize, SMEM_QK);

    k_embed<<<T_, 256>>>(ids, embed_W);
    k_convqkv<<<dim3(1024, 6), 256>>>(wq, wk, wv);
    k_convw5<<<dim3(8192, 5), 256>>>(wo, w1, w3, w2, lm);

    for (int l = 0; l < NL; l++) {
        // attention
        k_rmssplit<<<T_, 256>>>(p_h, n1 + (size_t)l*D_, p_xn, p_ah, p_al);
        k_mma256<<<dim3(16, 6), 256, SMEM_W>>>(p_ah, p_al,
            p_cqh + (size_t)l*D_*QKV_, p_cql + (size_t)l*D_*QKV_, p_qkv, D_, QKV_, QKV_, 0);
        k_ropesplit<<<T_, 192>>>();
        k_qk<<<dim3(4, 4, 64), 256, SMEM_QK>>>();
        k_softmax<<<NCK*NH*CH/8, 256>>>();
        k_avm<<<dim3(4, 1, 64), 256, SMEM_MMA128>>>();   // writes bf16 hi/lo into g_ah/g_al
        k_mma256<<<dim3(16, 4), 256, SMEM_W>>>(p_ah, p_al,
            p_cwoh + (size_t)l*D_*D_, p_cwol + (size_t)l*D_*D_, p_h, D_, D_, D_, 1);

        // MoE
        k_rmssplit<<<T_, 256>>>(p_h, n2 + (size_t)l*D_, p_xn, p_ah, p_al);
        k_router<<<T_/8, 256>>>(rw + (size_t)l*D_*NE);
        k_aux<<<1, 256>>>();
        k_bucket<<<T_/256, 256>>>();
        k_moe_mma<<<dim3(16, 16, NE), 256, SMEM_W>>>(
            p_c1h + (size_t)l*NE*D_*F_, p_c1l + (size_t)l*NE*D_*F_,
            p_c3h + (size_t)l*NE*D_*F_, p_c3l + (size_t)l*NE*D_*F_, 1);
        k_moe_mma<<<dim3(16, 4, NE), 256, SMEM_W>>>(
            p_c2h + (size_t)l*NE*F_*D_, p_c2l + (size_t)l*NE*F_*D_, nullptr, nullptr, 2);
        k_combine<<<T_, 256>>>();
    }

    // final norm + heads
    k_rmssplit<<<T_, 256>>>(p_h, normf, p_xn, p_ah, p_al);
    k_mma256<<<dim3(16, NV/256), 256, SMEM_W>>>(p_ah, p_al, p_clh, p_cll, out, D_, NV, NV, 0);
    k_task<<<16, 256>>>(tw, tb, out);
    k_mean1<<<16, 256>>>();
    k_mean2<<<4, 256>>>();
    k_eval<<<8, 256>>>(ew, eb, out);
    k_auxw<<<1, 1>>>(out);
}

// round 14
// speedup vs baseline: 1.0139x; 1.0139x over previous
#include <cuda_runtime.h>
#include <cuda_bf16.h>
#include <math.h>
#include <stdint.h>

#define T_   2048
#define D_   1024
#define NH   16
#define NKV  4
#define F_   2048
#define NE   8
#define NL   2
#define NV   32000
#define CH   512
#define NCK  4
#define QKV_ 1536

#define OUT_TASK   (T_*(size_t)NV)
#define OUT_EVAL   (OUT_TASK + 16)
#define OUT_AUX    (OUT_EVAL + 8)

typedef __nv_bfloat16 bf16;
typedef __nv_bfloat162 bf162;

// ---------------- scratch (device globals; no allocation) ----------------
__device__ float g_h   [(size_t)T_*D_];
__device__ float g_xn  [(size_t)T_*D_];
__device__ float g_qkv [(size_t)T_*QKV_];
__device__ float g_sc  [(size_t)NCK*NH*CH*CH];
__device__ float g_probs[(size_t)T_*NE];
__device__ int   g_ti  [T_*2];
__device__ float g_tw  [T_*2];
__device__ int   g_cnt [NE];
__device__ int   g_rows[NE*T_];
__device__ int   g_slot[T_*2];
__device__ float g_yb  [(size_t)NE*T_*D_];
__device__ float g_aux [1];
__device__ float g_xm  [D_];
__device__ float g_mp  [16*D_];
__device__ bf16  g_ah  [(size_t)T_*D_];
__device__ bf16  g_al  [(size_t)T_*D_];
__device__ bf16  g_qkvh[(size_t)T_*QKV_];
__device__ bf16  g_qkvl[(size_t)T_*QKV_];
__device__ float g_ub  [(size_t)NE*T_*F_];
__device__ bf16  g_hbh [(size_t)NE*T_*F_];   // also reused as P hi
__device__ bf16  g_hbl [(size_t)NE*T_*F_];   // also reused as P lo
// pre-converted weights (hi/lo bf16)
__device__ bf16  c_qkvh[(size_t)NL*D_*QKV_], c_qkvl[(size_t)NL*D_*QKV_];
__device__ bf16  c_woh [(size_t)NL*D_*D_],   c_wol [(size_t)NL*D_*D_];
__device__ bf16  c_w1h [(size_t)NL*NE*D_*F_], c_w1l[(size_t)NL*NE*D_*F_];
__device__ bf16  c_w3h [(size_t)NL*NE*D_*F_], c_w3l[(size_t)NL*NE*D_*F_];
__device__ bf16  c_w2h [(size_t)NL*NE*F_*D_], c_w2l[(size_t)NL*NE*F_*D_];
__device__ bf16  c_lmh [(size_t)D_*NV],      c_lml[(size_t)D_*NV];

// ---------------- asm helpers ----------------
__device__ __forceinline__ uint32_t smem_u32(const void* p) {
    uint32_t a;
    asm("{ .reg .u64 t; cvta.to.shared.u64 t, %1; cvt.u32.u64 %0, t; }" : "=r"(a) : "l"(p));
    return a;
}
__device__ __forceinline__ void cpa(uint32_t d, const void* s) {
    asm volatile("cp.async.cg.shared.global [%0], [%1], 16;" :: "r"(d), "l"(s));
}
__device__ __forceinline__ void cp_commit() { asm volatile("cp.async.commit_group;" ::: "memory"); }
__device__ __forceinline__ void cp_wait1()  { asm volatile("cp.async.wait_group 1;" ::: "memory"); }
__device__ __forceinline__ void cp_wait0()  { asm volatile("cp.async.wait_group 0;" ::: "memory"); }
__device__ __forceinline__ void ldsm4(uint32_t (&r)[4], uint32_t a) {
    asm volatile("ldmatrix.sync.aligned.m8n8.x4.shared.b16 {%0,%1,%2,%3}, [%4];"
        : "=r"(r[0]), "=r"(r[1]), "=r"(r[2]), "=r"(r[3]) : "r"(a));
}
__device__ __forceinline__ void ldsm4t(uint32_t (&r)[4], uint32_t a) {
    asm volatile("ldmatrix.sync.aligned.m8n8.x4.trans.shared.b16 {%0,%1,%2,%3}, [%4];"
        : "=r"(r[0]), "=r"(r[1]), "=r"(r[2]), "=r"(r[3]) : "r"(a));
}
__device__ __forceinline__ void ldsm2t(uint32_t (&r)[2], uint32_t a) {
    asm volatile("ldmatrix.sync.aligned.m8n8.x2.trans.shared.b16 {%0,%1}, [%2];"
        : "=r"(r[0]), "=r"(r[1]) : "r"(a));
}
__device__ __forceinline__ void ldsm2(uint32_t (&r)[2], uint32_t a) {
    asm volatile("ldmatrix.sync.aligned.m8n8.x2.shared.b16 {%0,%1}, [%2];"
        : "=r"(r[0]), "=r"(r[1]) : "r"(a));
}
__device__ __forceinline__ void mma16816(float (&d)[4], const uint32_t (&a)[4], const uint32_t (&b)[2]) {
    asm volatile("mma.sync.aligned.m16n8k16.row.col.f32.bf16.bf16.f32 "
        "{%0,%1,%2,%3}, {%4,%5,%6,%7}, {%8,%9}, {%0,%1,%2,%3};"
        : "+f"(d[0]), "+f"(d[1]), "+f"(d[2]), "+f"(d[3])
        : "r"(a[0]), "r"(a[1]), "r"(a[2]), "r"(a[3]), "r"(b[0]), "r"(b[1]));
}

// ============== 128x256 tile GEMM (main path) ==============
// per buffer: Ah 128x80B @0 | Al @10240 | Bh 32x528B @20480 | Bl @37376
#define W_OFF_AL 10240
#define W_OFF_BH 20480
#define W_OFF_BL 37376
#define W_BUFSZ  54272
#define SMEM_W   (3*W_BUFSZ)

// modes: 0 = C=acc, 1 = C+=acc, 2 = silu(U)*acc -> split bf16 to Hh/Hl
__device__ __forceinline__ void mma_block256(
    const bf16* __restrict__ Ah, const bf16* __restrict__ Al, int lda,
    const int* __restrict__ rows, int count, int m0,
    const bf16* __restrict__ Bh, const bf16* __restrict__ Bl, int ldb, int n0,
    int K, float* __restrict__ C, int ldc, int mode,
    const float* __restrict__ U, bf16* __restrict__ Hh, bf16* __restrict__ Hl,
    char* dsm, uint32_t sb)
{
    const int tid = threadIdx.x, lane = tid & 31, wid = tid >> 5;
    const int wm = (wid & 1) * 64, wn = (wid >> 1) * 64;
    const int ar = tid >> 1, akc = (tid & 1) * 16;
    const int gm = m0 + ar;
    const bool av = gm < count;
    const bf16 *pAh = nullptr, *pAl = nullptr;
    if (av) {
        size_t rr = (size_t)(rows ? rows[gm] : gm) * lda + akc;
        pAh = Ah + rr; pAl = Al + rr;
    }
    const uint32_t ao = (uint32_t)ar * 80 + (uint32_t)akc * 2;

    if (!av) {
        uint4 z = make_uint4(0,0,0,0);
        #pragma unroll
        for (int s = 0; s < 3; s++) {
            char* bb = dsm + s * W_BUFSZ;
            *(uint4*)(bb + ao) = z;              *(uint4*)(bb + ao + 16) = z;
            *(uint4*)(bb + W_OFF_AL + ao) = z;   *(uint4*)(bb + W_OFF_AL + ao + 16) = z;
        }
    }

    float acc[4][8][4];
    #pragma unroll
    for (int a = 0; a < 4; a++)
        #pragma unroll
        for (int b = 0; b < 8; b++)
            #pragma unroll
            for (int c = 0; c < 4; c++) acc[a][b][c] = 0.f;

    auto ISSUE = [&](int k0, uint32_t sbuf) {
        if (av) {
            cpa(sbuf + ao,                 pAh + k0);
            cpa(sbuf + ao + 16,            pAh + k0 + 8);
            cpa(sbuf + W_OFF_AL + ao,      pAl + k0);
            cpa(sbuf + W_OFF_AL + ao + 16, pAl + k0 + 8);
        }
        #pragma unroll
        for (int j = 0; j < 4; j++) {
            int u = tid + j * 256;
            int row = u >> 5, c16 = u & 31;
            uint32_t doff = (uint32_t)row * 528 + (uint32_t)c16 * 16;
            const bf16* sh = Bh + (size_t)(k0 + row) * ldb + n0 + c16 * 8;
            const bf16* sl = Bl + (size_t)(k0 + row) * ldb + n0 + c16 * 8;
            cpa(sbuf + W_OFF_BH + doff, sh);
            cpa(sbuf + W_OFF_BL + doff, sl);
        }
    };

    auto COMPUTE = [&](uint32_t boff) {
        uint32_t abase = sb + boff + (uint32_t)(wm + (lane & 15)) * 80 + ((lane >> 4) * 16);
        uint32_t klocal = (uint32_t)((lane & 7) + ((lane >> 3) & 1) * 8);
        uint32_t bcol = (uint32_t)(wn + ((lane >> 4) & 1) * 8);
        #pragma unroll
        for (int ks = 0; ks < 2; ks++) {
            uint32_t ah4[4][4], al4[4][4];
            #pragma unroll
            for (int mt = 0; mt < 4; mt++) {
                uint32_t aa = abase + mt * (16 * 80) + ks * 32;
                ldsm4(ah4[mt], aa);
                ldsm4(al4[mt], aa + W_OFF_AL);
            }
            uint32_t bh[4][4], bl[4][4];
            uint32_t bkb = sb + boff + W_OFF_BH + (klocal + ks * 16) * 528 + bcol * 2;
            #pragma unroll
            for (int ng = 0; ng < 4; ng++) {
                uint32_t ba = bkb + ng * 32;   // 16 cols * 2B
                ldsm4t(bh[ng], ba);
                ldsm4t(bl[ng], ba + (W_OFF_BL - W_OFF_BH));
            }
            #pragma unroll
            for (int mt = 0; mt < 4; mt++)
                #pragma unroll
                for (int nt = 0; nt < 8; nt++) {
                    const int ng = nt >> 1, hf = (nt & 1) * 2;
                    uint32_t bhf[2] = { bh[ng][hf], bh[ng][hf + 1] };
                    uint32_t blf[2] = { bl[ng][hf], bl[ng][hf + 1] };
                    mma16816(acc[mt][nt], ah4[mt], bhf);
                    mma16816(acc[mt][nt], ah4[mt], blf);
                    mma16816(acc[mt][nt], al4[mt], bhf);
                }
        }
    };

    const int NC = K >> 5;
    ISSUE(0, sb); cp_commit();
    if (NC > 1) { ISSUE(32, sb + W_BUFSZ); cp_commit(); }
    for (int c = 0; c < NC; c++) {
        if (c == NC - 1) cp_wait0(); else cp_wait1();
        __syncthreads();
        COMPUTE((uint32_t)(c % 3) * W_BUFSZ);
        if (c + 2 < NC) { ISSUE((c + 2) << 5, sb + (uint32_t)((c + 2) % 3) * W_BUFSZ); cp_commit(); }
    }

    #pragma unroll
    for (int mt = 0; mt < 4; mt++) {
        int r0 = m0 + wm + mt * 16 + (lane >> 2);
        #pragma unroll
        for (int nt = 0; nt < 8; nt++) {
            int cc = n0 + wn + nt * 8 + (lane & 3) * 2;
            float* d = acc[mt][nt];
            #pragma unroll
            for (int hrow = 0; hrow < 2; hrow++) {
                int r = r0 + hrow * 8;
                if (r >= count) continue;
                float d0 = d[hrow*2], d1 = d[hrow*2 + 1];
                size_t o = (size_t)r * ldc + cc;
                if (mode == 0) {
                    *(float2*)(C + o) = make_float2(d0, d1);
                } else if (mode == 1) {
                    float2 p = *(const float2*)(C + o);
                    *(float2*)(C + o) = make_float2(p.x + d0, p.y + d1);
                } else {
                    float2 u = *(const float2*)(U + o);
                    float h0 = (u.x / (1.f + expf(-u.x))) * d0;
                    float h1 = (u.y / (1.f + expf(-u.y))) * d1;
                    bf162 hh = __floats2bfloat162_rn(h0, h1);
                    bf162 ll = __floats2bfloat162_rn(h0 - __low2float(hh), h1 - __high2float(hh));
                    *(bf162*)(Hh + o) = hh;
                    *(bf162*)(Hl + o) = ll;
                }
            }
        }
    }
}

// dense GEMM: grid (M/128, N/256)
__global__ __launch_bounds__(256, 1) void k_mma256(
    const bf16* __restrict__ Ah, const bf16* __restrict__ Al,
    const bf16* __restrict__ Bh, const bf16* __restrict__ Bl,
    float* __restrict__ C, int K, int ldb, int ldc, int mode)
{
    extern __shared__ __align__(16) char dsm[];
    mma_block256(Ah, Al, K, nullptr, 1 << 30, blockIdx.x * 128,
                 Bh, Bl, ldb, blockIdx.y * 256,
                 K, C, ldc, mode, nullptr, nullptr, nullptr, dsm, smem_u32(dsm));
}

// MoE: which 0 = X W1 -> g_ub; 1 = X W3 fused silu -> hidden split; 2 = H W2 -> g_yb
__global__ __launch_bounds__(256, 1) void k_moe_mma(
    const bf16* __restrict__ Wh, const bf16* __restrict__ Wl, int which)
{
    int e = blockIdx.z;
    int count = g_cnt[e];
    int m0 = blockIdx.x * 128;
    if (m0 >= count) return;
    int n0 = blockIdx.y * 256;
    extern __shared__ __align__(16) char dsm[];
    uint32_t sb = smem_u32(dsm);
    if (which == 0) {
        mma_block256(g_ah, g_al, D_, g_rows + e * T_, count, m0,
                     Wh + (size_t)e * D_ * F_, Wl + (size_t)e * D_ * F_, F_, n0,
                     D_, g_ub + (size_t)e * T_ * F_, F_, 0, nullptr, nullptr, nullptr, dsm, sb);
    } else if (which == 1) {
        mma_block256(g_ah, g_al, D_, g_rows + e * T_, count, m0,
                     Wh + (size_t)e * D_ * F_, Wl + (size_t)e * D_ * F_, F_, n0,
                     D_, nullptr, F_, 2, g_ub + (size_t)e * T_ * F_,
                     g_hbh + (size_t)e * T_ * F_, g_hbl + (size_t)e * T_ * F_, dsm, sb);
    } else {
        mma_block256(g_hbh + (size_t)e * T_ * F_, g_hbl + (size_t)e * T_ * F_, F_, nullptr, count, m0,
                     Wh + (size_t)e * F_ * D_, Wl + (size_t)e * F_ * D_, D_, n0,
                     F_, g_yb + (size_t)e * T_ * D_, D_, 0, nullptr, nullptr, nullptr, dsm, sb);
    }
}

// ============== 128x128 tile path (k_avm only, nlim=64) ==============
#define OFF_AL 10240
#define OFF_BH 20480
#define OFF_BL 29184
#define BUFSZ  37888
#define SMEM_MMA128 (3*BUFSZ)

// mode 0: fp32 C; mode 3: split-store bf16 hi/lo to Hh/Hl
__device__ __forceinline__ void mma_block128(
    const bf16* __restrict__ Ah, const bf16* __restrict__ Al, int lda,
    int count, int m0,
    const bf16* __restrict__ Bh, const bf16* __restrict__ Bl, int ldb, int n0, int nlim,
    int K, float* __restrict__ C, bf16* __restrict__ Hh, bf16* __restrict__ Hl, int ldc,
    int mode, char* dsm, uint32_t sb)
{
    const int tid = threadIdx.x, lane = tid & 31, wid = tid >> 5;
    const int wm = (wid & 1) * 64, wn = (wid >> 1) * 32;
    const int ar = tid >> 1, akc = (tid & 1) * 16;
    const int bkr = tid >> 3, bn16 = (tid & 7) * 16;
    const int gm = m0 + ar;
    const bool av = gm < count;
    const bf16 *pAh = nullptr, *pAl = nullptr;
    if (av) {
        size_t rr = (size_t)gm * lda + akc;
        pAh = Ah + rr; pAl = Al + rr;
    }
    const int bcol = (nlim < 128) ? (bn16 & (nlim - 1)) : bn16;
    const bf16* pBh = Bh + (size_t)bkr * ldb + n0 + bcol;
    const bf16* pBl = Bl + (size_t)bkr * ldb + n0 + bcol;
    const uint32_t ao = (uint32_t)ar * 80 + (uint32_t)akc * 2;
    const uint32_t bo = (uint32_t)OFF_BH + (uint32_t)bkr * 272 + (uint32_t)bn16 * 2;

    if (!av) {
        uint4 z = make_uint4(0,0,0,0);
        #pragma unroll
        for (int s = 0; s < 3; s++) {
            char* bb = dsm + s * BUFSZ;
            *(uint4*)(bb + ao) = z;            *(uint4*)(bb + ao + 16) = z;
            *(uint4*)(bb + OFF_AL + ao) = z;   *(uint4*)(bb + OFF_AL + ao + 16) = z;
        }
    }

    float acc[4][4][4];
    #pragma unroll
    for (int a = 0; a < 4; a++)
        #pragma unroll
        for (int b = 0; b < 4; b++)
            #pragma unroll
            for (int c = 0; c < 4; c++) acc[a][b][c] = 0.f;

    auto ISSUE = [&](int k0, uint32_t sbuf) {
        if (av) {
            cpa(sbuf + ao,               pAh + k0);
            cpa(sbuf + ao + 16,          pAh + k0 + 8);
            cpa(sbuf + OFF_AL + ao,      pAl + k0);
            cpa(sbuf + OFF_AL + ao + 16, pAl + k0 + 8);
        }
        const bf16* b = pBh + (size_t)k0 * ldb;
        cpa(sbuf + bo,      b);
        cpa(sbuf + bo + 16, b + 8);
        b = pBl + (size_t)k0 * ldb;
        cpa(sbuf + (OFF_BL - OFF_BH) + bo,      b);
        cpa(sbuf + (OFF_BL - OFF_BH) + bo + 16, b + 8);
    };

    auto COMPUTE = [&](uint32_t boff) {
        uint32_t abase = sb + boff + (uint32_t)(wm + (lane & 15)) * 80 + ((lane >> 4) * 8) * 2;
        uint32_t bbase = sb + boff + OFF_BH
                       + (uint32_t)((lane & 7) + ((lane >> 3) & 1) * 8) * 272
                       + (uint32_t)wn * 2;
        #pragma unroll
        for (int ks = 0; ks < 2; ks++) {
            uint32_t ah4[4][4], al4[4][4], bh2[4][2], bl2[4][2];
            #pragma unroll
            for (int mt = 0; mt < 4; mt++) {
                uint32_t aa = abase + mt * (16 * 80) + ks * 32;
                ldsm4(ah4[mt], aa);
                ldsm4(al4[mt], aa + OFF_AL);
            }
            #pragma unroll
            for (int nt = 0; nt < 4; nt++) {
                uint32_t ba = bbase + ks * (16 * 272) + nt * 16;
                ldsm2t(bh2[nt], ba);
                ldsm2t(bl2[nt], ba + (OFF_BL - OFF_BH));
            }
            #pragma unroll
            for (int mt = 0; mt < 4; mt++)
                #pragma unroll
                for (int nt = 0; nt < 4; nt++) {
                    mma16816(acc[mt][nt], ah4[mt], bh2[nt]);
                    mma16816(acc[mt][nt], ah4[mt], bl2[nt]);
                    mma16816(acc[mt][nt], al4[mt], bh2[nt]);
                }
        }
    };

    const int NC = K >> 5;
    ISSUE(0, sb); cp_commit();
    if (NC > 1) { ISSUE(32, sb + BUFSZ); cp_commit(); }
    for (int c = 0; c < NC; c++) {
        if (c == NC - 1) cp_wait0(); else cp_wait1();
        __syncthreads();
        COMPUTE((uint32_t)(c % 3) * BUFSZ);
        if (c + 2 < NC) { ISSUE((c + 2) << 5, sb + (uint32_t)((c + 2) % 3) * BUFSZ); cp_commit(); }
    }

    #pragma unroll
    for (int mt = 0; mt < 4; mt++) {
        int r0 = m0 + wm + mt * 16 + (lane >> 2);
        #pragma unroll
        for (int nt = 0; nt < 4; nt++) {
            int ln = wn + nt * 8 + (lane & 3) * 2;
            if (ln >= nlim) continue;
            int cc = n0 + ln;
            float* d = acc[mt][nt];
            #pragma unroll
            for (int hrow = 0; hrow < 2; hrow++) {
                int r = r0 + hrow * 8;
                if (r >= count) continue;
                float d0 = d[hrow*2], d1 = d[hrow*2 + 1];
                size_t o = (size_t)r * ldc + cc;
                if (mode == 0) {
                    *(float2*)(C + o) = make_float2(d0, d1);
                } else {
                    bf162 hh = __floats2bfloat162_rn(d0, d1);
                    bf162 ll = __floats2bfloat162_rn(d0 - __low2float(hh), d1 - __high2float(hh));
                    *(bf162*)(Hh + o) = hh;
                    *(bf162*)(Hl + o) = ll;
                }
            }
        }
    }
}

// O = P V: grid (4, 1, 64); writes bf16 hi/lo DIRECTLY into g_ah/g_al
// (the rms split there is dead by the time attention output is formed);
// K trimmed by causality (P rows in [m0,m0+128) are zero beyond col m0+127)
__global__ __launch_bounds__(256, 1) void k_avm()
{
    int b = blockIdx.z, chunk = b >> 4, head = b & 15, kvh = head >> 2;
    int m0 = blockIdx.x * 128;
    extern __shared__ __align__(16) char dsm[];
    size_t obase = (size_t)chunk * CH * D_ + head * 64;
    mma_block128(g_hbh + (size_t)b * CH * CH, g_hbl + (size_t)b * CH * CH, CH, CH, m0,
                 g_qkvh + (size_t)chunk * CH * QKV_ + 1280 + kvh * 64,
                 g_qkvl + (size_t)chunk * CH * QKV_ + 1280 + kvh * 64, QKV_, 0, 64,
                 m0 + 128, nullptr, g_ah + obase, g_al + obase, D_, 3, dsm, smem_u32(dsm));
}

// ---------------- scores S = Q K^T: grid (4, 4, 64); skips n0>m0 tiles ----------------
#define QK_AL 10240
#define QK_KH 20480
#define QK_KL 30720
#define QK_BUF 40960
#define SMEM_QK (2*QK_BUF)

__global__ __launch_bounds__(256, 1) void k_qk()
{
    if (blockIdx.y > blockIdx.x) return;
    extern __shared__ __align__(16) char dsm[];
    uint32_t sb = smem_u32(dsm);
    int b = blockIdx.z, chunk = b >> 4, head = b & 15, kvh = head >> 2;
    int m0 = blockIdx.x * 128, n0 = blockIdx.y * 128;
    int tid = threadIdx.x, lane = tid & 31, wid = tid >> 5;
    int wm = (wid & 1) * 64, wn = (wid >> 1) * 32;
    int ar = tid >> 1, akc = (tid & 1) * 16;
    const bf16* pQh = g_qkvh + (size_t)(chunk*CH + m0 + ar) * QKV_ + head * 64 + akc;
    const bf16* pQl = g_qkvl + (size_t)(chunk*CH + m0 + ar) * QKV_ + head * 64 + akc;
    const bf16* pKh = g_qkvh + (size_t)(chunk*CH + n0 + ar) * QKV_ + 1024 + kvh * 64 + akc;
    const bf16* pKl = g_qkvl + (size_t)(chunk*CH + n0 + ar) * QKV_ + 1024 + kvh * 64 + akc;
    const uint32_t ao = (uint32_t)ar * 80 + (uint32_t)akc * 2;

    float acc[4][4][4];
    #pragma unroll
    for (int a = 0; a < 4; a++)
        #pragma unroll
        for (int bb = 0; bb < 4; bb++)
            #pragma unroll
            for (int c = 0; c < 4; c++) acc[a][bb][c] = 0.f;

    auto ISSUE = [&](int k0, uint32_t sbuf) {
        cpa(sbuf + ao,               pQh + k0); cpa(sbuf + ao + 16,           pQh + k0 + 8);
        cpa(sbuf + QK_AL + ao,       pQl + k0); cpa(sbuf + QK_AL + ao + 16,   pQl + k0 + 8);
        cpa(sbuf + QK_KH + ao,       pKh + k0); cpa(sbuf + QK_KH + ao + 16,   pKh + k0 + 8);
        cpa(sbuf + QK_KL + ao,       pKl + k0); cpa(sbuf + QK_KL + ao + 16,   pKl + k0 + 8);
    };
    auto COMPUTE = [&](uint32_t boff) {
        uint32_t abase = sb + boff + (uint32_t)(wm + (lane & 15)) * 80 + ((lane >> 4) * 8) * 2;
        #pragma unroll
        for (int ks = 0; ks < 2; ks++) {
            uint32_t ah4[4][4], al4[4][4], bh2[4][2], bl2[4][2];
            #pragma unroll
            for (int mt = 0; mt < 4; mt++) {
                uint32_t aa = abase + mt * (16 * 80) + ks * 32;
                ldsm4(ah4[mt], aa);
                ldsm4(al4[mt], aa + QK_AL);
            }
            #pragma unroll
            for (int nt = 0; nt < 4; nt++) {
                uint32_t ba = sb + boff + QK_KH
                            + (uint32_t)(wn + nt * 8 + (lane & 7)) * 80
                            + ks * 32 + ((lane >> 3) & 1) * 16;
                ldsm2(bh2[nt], ba);
                ldsm2(bl2[nt], ba + (QK_KL - QK_KH));
            }
            #pragma unroll
            for (int mt = 0; mt < 4; mt++)
                #pragma unroll
                for (int nt = 0; nt < 4; nt++) {
                    mma16816(acc[mt][nt], ah4[mt], bh2[nt]);
                    mma16816(acc[mt][nt], ah4[mt], bl2[nt]);
                    mma16816(acc[mt][nt], al4[mt], bh2[nt]);
                }
        }
    };

    ISSUE(0, sb); cp_commit();
    ISSUE(32, sb + QK_BUF); cp_commit();
    cp_wait1(); __syncthreads(); COMPUTE(0);
    cp_wait0(); __syncthreads(); COMPUTE(QK_BUF);

    float* S = g_sc + (size_t)b * CH * CH;
    #pragma unroll
    for (int mt = 0; mt < 4; mt++) {
        int r0 = wm + mt * 16 + (lane >> 2);
        #pragma unroll
        for (int nt = 0; nt < 4; nt++) {
            int c0 = wn + nt * 8 + (lane & 3) * 2;
            float* d = acc[mt][nt];
            #pragma unroll
            for (int hrow = 0; hrow < 2; hrow++) {
                int qg = m0 + r0 + hrow * 8;
                int kg = n0 + c0;
                float v0 = d[hrow*2] * 0.125f, v1 = d[hrow*2 + 1] * 0.125f;
                if (kg > qg)     v0 = -1e30f;
                if (kg + 1 > qg) v1 = -1e30f;
                *(float2*)(S + (size_t)qg * CH + kg) = make_float2(v0, v1);
            }
        }
    }
}

// qkv weight segments: grid (1024, 6)
__global__ void k_convqkv(const float* __restrict__ wq, const float* __restrict__ wk,
                          const float* __restrict__ wv) {
    int seg = blockIdx.y, l = seg / 3, which = seg - l * 3;
    const float* src; int N; size_t doff;
    if (which == 0)      { src = wq + (size_t)l*D_*1024; N = 1024; doff = (size_t)l*D_*QKV_; }
    else if (which == 1) { src = wk + (size_t)l*D_*256;  N = 256;  doff = (size_t)l*D_*QKV_ + 1024; }
    else                 { src = wv + (size_t)l*D_*256;  N = 256;  doff = (size_t)l*D_*QKV_ + 1280; }
    size_t i = (size_t)blockIdx.x * 256 + threadIdx.x;
    size_t e = i * 4;
    if (e >= (size_t)D_ * N) return;
    int r = (int)(e / N), c = (int)(e % N);
    float4 v = *(const float4*)(src + e);
    size_t o = doff + (size_t)r * QKV_ + c;
    bf162 h0 = __floats2bfloat162_rn(v.x, v.y);
    bf162 l0 = __floats2bfloat162_rn(v.x - __low2float(h0), v.y - __high2float(h0));
    bf162 h1 = __floats2bfloat162_rn(v.z, v.w);
    bf162 l1 = __floats2bfloat162_rn(v.z - __low2float(h1), v.w - __high2float(h1));
    *(bf162*)(c_qkvh+o) = h0; *(bf162*)(c_qkvh+o+2) = h1;
    *(bf162*)(c_qkvl+o) = l0; *(bf162*)(c_qkvl+o+2) = l1;
}

// wo/w1/w3/w2/lm: grid-stride, streaming loads/stores, 16 floats/thread
__global__ void k_convw5(const float* __restrict__ wo, const float* __restrict__ w1,
                         const float* __restrict__ w3, const float* __restrict__ w2,
                         const float* __restrict__ lm) {
    int y = blockIdx.y;
    const float* src; bf16 *dh, *dl; size_t n;
    if (y == 0)      { src = wo; dh = c_woh; dl = c_wol; n = (size_t)NL*D_*D_; }
    else if (y == 1) { src = w1; dh = c_w1h; dl = c_w1l; n = (size_t)NL*NE*D_*F_; }
    else if (y == 2) { src = w3; dh = c_w3h; dl = c_w3l; n = (size_t)NL*NE*D_*F_; }
    else if (y == 3) { src = w2; dh = c_w2h; dl = c_w2l; n = (size_t)NL*NE*F_*D_; }
    else             { src = lm; dh = c_lmh; dl = c_lml; n = (size_t)D_*NV; }
    size_t nchunks = n >> 4;
    size_t stride = (size_t)gridDim.x * 256;
    const float4* xv = (const float4*)src;
    for (size_t i = (size_t)blockIdx.x * 256 + threadIdx.x; i < nchunks; i += stride) {
        float4 a = __ldcs(xv + 4*i);
        float4 b = __ldcs(xv + 4*i + 1);
        float4 c = __ldcs(xv + 4*i + 2);
        float4 d = __ldcs(xv + 4*i + 3);
        bf162 h0 = __floats2bfloat162_rn(a.x, a.y), h1 = __floats2bfloat162_rn(a.z, a.w);
        bf162 h2 = __floats2bfloat162_rn(b.x, b.y), h3 = __floats2bfloat162_rn(b.z, b.w);
        bf162 h4 = __floats2bfloat162_rn(c.x, c.y), h5 = __floats2bfloat162_rn(c.z, c.w);
        bf162 h6 = __floats2bfloat162_rn(d.x, d.y), h7 = __floats2bfloat162_rn(d.z, d.w);
        bf162 l0 = __floats2bfloat162_rn(a.x - __low2float(h0), a.y - __high2float(h0));
        bf162 l1 = __floats2bfloat162_rn(a.z - __low2float(h1), a.w - __high2float(h1));
        bf162 l2 = __floats2bfloat162_rn(b.x - __low2float(h2), b.y - __high2float(h2));
        bf162 l3 = __floats2bfloat162_rn(b.z - __low2float(h3), b.w - __high2float(h3));
        bf162 l4 = __floats2bfloat162_rn(c.x - __low2float(h4), c.y - __high2float(h4));
        bf162 l5 = __floats2bfloat162_rn(c.z - __low2float(h5), c.w - __high2float(h5));
        bf162 l6 = __floats2bfloat162_rn(d.x - __low2float(h6), d.y - __high2float(h6));
        bf162 l7 = __floats2bfloat162_rn(d.z - __low2float(h7), d.w - __high2float(h7));
        __stcs((uint4*)dh + 2*i,     make_uint4(*(uint32_t*)&h0, *(uint32_t*)&h1, *(uint32_t*)&h2, *(uint32_t*)&h3));
        __stcs((uint4*)dh + 2*i + 1, make_uint4(*(uint32_t*)&h4, *(uint32_t*)&h5, *(uint32_t*)&h6, *(uint32_t*)&h7));
        __stcs((uint4*)dl + 2*i,     make_uint4(*(uint32_t*)&l0, *(uint32_t*)&l1, *(uint32_t*)&l2, *(uint32_t*)&l3));
        __stcs((uint4*)dl + 2*i + 1, make_uint4(*(uint32_t*)&l4, *(uint32_t*)&l5, *(uint32_t*)&l6, *(uint32_t*)&l7));
    }
}

// ---------------- fused rms + split ----------------
__global__ void k_rmssplit(const float* __restrict__ x, const float* __restrict__ w,
                           float* __restrict__ out, bf16* __restrict__ hh, bf16* __restrict__ ll) {
    int t = blockIdx.x, tid = threadIdx.x;
    __shared__ float sh[256];
    float4 v = ((const float4*)(x + (size_t)t*D_))[tid];
    float s = v.x*v.x + v.y*v.y + v.z*v.z + v.w*v.w;
    sh[tid] = s; __syncthreads();
    for (int o = 128; o > 0; o >>= 1) { if (tid < o) sh[tid] += sh[tid+o]; __syncthreads(); }
    float scale = rsqrtf(sh[0] / (float)D_ + 1e-6f);
    float4 wv = ((const float4*)w)[tid];
    float4 o;
    o.x = wv.x * v.x * scale; o.y = wv.y * v.y * scale;
    o.z = wv.z * v.z * scale; o.w = wv.w * v.w * scale;
    ((float4*)(out + (size_t)t*D_))[tid] = o;
    bf162 h0 = __floats2bfloat162_rn(o.x, o.y);
    bf162 h1 = __floats2bfloat162_rn(o.z, o.w);
    bf162 l0 = __floats2bfloat162_rn(o.x - __low2float(h0), o.y - __high2float(h0));
    bf162 l1 = __floats2bfloat162_rn(o.z - __low2float(h1), o.w - __high2float(h1));
    ((uint2*)(hh + (size_t)t*D_))[tid] = make_uint2(*(uint32_t*)&h0, *(uint32_t*)&h1);
    ((uint2*)(ll + (size_t)t*D_))[tid] = make_uint2(*(uint32_t*)&l0, *(uint32_t*)&l1);
}

// ---------------- fused rope + qkv split: grid T_, 192 threads ----------------
__global__ void k_ropesplit() {
    int t = blockIdx.x, tid = threadIdx.x;
    int c0 = tid * 8;
    float p = (float)(t & (CH-1));
    const float* base = g_qkv + (size_t)t * QKV_;
    float4 a = *(const float4*)(base + c0);
    float4 b = *(const float4*)(base + c0 + 4);
    float vv[8] = {a.x, a.y, a.z, a.w, b.x, b.y, b.z, b.w};
    if (c0 < 1280) {
        #pragma unroll
        for (int j = 0; j < 4; j++) {
            int c = c0 + 2*j;
            int i = (c & 63) >> 1;
            float ang = p * powf(1000000.0f, -(float)i/32.0f);
            float cs = cosf(ang), sn = sinf(ang);
            float x1 = vv[2*j], x2 = vv[2*j+1];
            vv[2*j]   = x1*cs - x2*sn;
            vv[2*j+1] = x1*sn + x2*cs;
        }
    }
    bf162 h[4], l[4];
    #pragma unroll
    for (int j = 0; j < 4; j++) {
        h[j] = __floats2bfloat162_rn(vv[2*j], vv[2*j+1]);
        l[j] = __floats2bfloat162_rn(vv[2*j] - __low2float(h[j]), vv[2*j+1] - __high2float(h[j]));
    }
    size_t o = ((size_t)t * QKV_ + c0) >> 3;
    ((uint4*)g_qkvh)[o] = make_uint4(*(uint32_t*)&h[0], *(uint32_t*)&h[1], *(uint32_t*)&h[2], *(uint32_t*)&h[3]);
    ((uint4*)g_qkvl)[o] = make_uint4(*(uint32_t*)&l[0], *(uint32_t*)&l[1], *(uint32_t*)&l[2], *(uint32_t*)&l[3]);
}

// ---------------- misc kernels ----------------
__global__ void k_embed(const int* __restrict__ ids, const float* __restrict__ ew) {
    int t = blockIdx.x;
    if (t == 0 && threadIdx.x == 0) g_aux[0] = 0.f;
    size_t r = (size_t)ids[t] * D_;
    for (int d = threadIdx.x; d < D_; d += blockDim.x) g_h[(size_t)t*D_ + d] = ew[r + d];
}
// warp-per-row softmax: reads fp32 S, writes P as bf16 hi/lo
__global__ void k_softmax() {
    int tid = threadIdx.x, lane = tid & 31, w = tid >> 5;
    int row = blockIdx.x * 8 + w;
    int q = row & (CH-1);
    const float* r = g_sc + (size_t)row * CH;
    float x[16];
    float mx = -1e30f;
    #pragma unroll
    for (int j = 0; j < 4; j++) {
        int c = j * 128 + lane * 4;
        float4 v = *(const float4*)(r + c);
        x[4*j]   = (c   <= q) ? v.x : -1e30f;
        x[4*j+1] = (c+1 <= q) ? v.y : -1e30f;
        x[4*j+2] = (c+2 <= q) ? v.z : -1e30f;
        x[4*j+3] = (c+3 <= q) ? v.w : -1e30f;
        mx = fmaxf(mx, fmaxf(fmaxf(x[4*j], x[4*j+1]), fmaxf(x[4*j+2], x[4*j+3])));
    }
    #pragma unroll
    for (int o = 16; o > 0; o >>= 1) mx = fmaxf(mx, __shfl_xor_sync(0xffffffffu, mx, o));
    float sum = 0.f;
    #pragma unroll
    for (int j = 0; j < 16; j++) { x[j] = (x[j] > -1e29f) ? expf(x[j] - mx) : 0.f; sum += x[j]; }
    #pragma unroll
    for (int o = 16; o > 0; o >>= 1) sum += __shfl_xor_sync(0xffffffffu, sum, o);
    float inv = 1.f / sum;
    #pragma unroll
    for (int j = 0; j < 4; j++) {
        int c = j * 128 + lane * 4;
        float p0 = x[4*j]*inv, p1 = x[4*j+1]*inv, p2 = x[4*j+2]*inv, p3 = x[4*j+3]*inv;
        bf162 h0 = __floats2bfloat162_rn(p0, p1);
        bf162 h1 = __floats2bfloat162_rn(p2, p3);
        bf162 l0 = __floats2bfloat162_rn(p0 - __low2float(h0), p1 - __high2float(h0));
        bf162 l1 = __floats2bfloat162_rn(p2 - __low2float(h1), p3 - __high2float(h1));
        size_t o = ((size_t)row * CH + c) >> 2;
        ((uint2*)g_hbh)[o] = make_uint2(*(uint32_t*)&h0, *(uint32_t*)&h1);
        ((uint2*)g_hbl)[o] = make_uint2(*(uint32_t*)&l0, *(uint32_t*)&l1);
    }
}
__global__ void k_router(const float* __restrict__ rw) {
    int tid = threadIdx.x, lane = tid & 31, w = tid >> 5;
    int t = blockIdx.x*8 + w;
    const float* xr = g_xn + (size_t)t*D_;
    float acc[NE] = {};
    for (int dd = 0; dd < 32; dd++) {
        int d = dd*32 + lane;
        float x = xr[d];
        const float* rr = rw + (size_t)d*NE;
        #pragma unroll
        for (int e = 0; e < NE; e++) acc[e] += x * rr[e];
    }
    #pragma unroll
    for (int e = 0; e < NE; e++)
        for (int o = 16; o > 0; o >>= 1) acc[e] += __shfl_down_sync(0xffffffffu, acc[e], o);
    if (lane == 0) {
        float m = acc[0];
        #pragma unroll
        for (int e = 1; e < NE; e++) m = fmaxf(m, acc[e]);
        float p[NE], s = 0.f;
        #pragma unroll
        for (int e = 0; e < NE; e++) { p[e] = expf(acc[e]-m); s += p[e]; }
        float inv = 1.f/s;
        #pragma unroll
        for (int e = 0; e < NE; e++) { p[e] *= inv; g_probs[(size_t)t*NE + e] = p[e]; }
        int i0 = 0;
        #pragma unroll
        for (int e = 1; e < NE; e++) if (p[e] > p[i0]) i0 = e;
        int i1 = (i0 == 0) ? 1 : 0;
        #pragma unroll
        for (int e = 0; e < NE; e++) if (e != i0 && p[e] > p[i1]) i1 = e;
        float ws = p[i0] + p[i1];
        g_ti[2*t] = i0; g_ti[2*t+1] = i1;
        g_tw[2*t] = p[i0]/ws; g_tw[2*t+1] = p[i1]/ws;
    }
}
// single-block aux accumulation; also zeroes g_cnt for k_bucket
__global__ void k_aux() {
    int tid = threadIdx.x;
    if (tid < NE) g_cnt[tid] = 0;
    __shared__ float sh[256];
    __shared__ float totp[NE], totc[NE];
    float ps[NE] = {}, cs[NE] = {};
    for (int t = tid; t < T_; t += 256) {
        cs[g_ti[2*t]] += 1.f;
        #pragma unroll
        for (int e = 0; e < NE; e++) ps[e] += g_probs[(size_t)t*NE + e];
    }
    for (int e = 0; e < NE; e++) {
        sh[tid] = ps[e]; __syncthreads();
        for (int o = 128; o > 0; o >>= 1) { if (tid < o) sh[tid] += sh[tid+o]; __syncthreads(); }
        if (tid == 0) totp[e] = sh[0];
        __syncthreads();
        sh[tid] = cs[e]; __syncthreads();
        for (int o = 128; o > 0; o >>= 1) { if (tid < o) sh[tid] += sh[tid+o]; __syncthreads(); }
        if (tid == 0) totc[e] = sh[0];
        __syncthreads();
    }
    if (tid == 0) {
        float a = 0.f;
        for (int e = 0; e < NE; e++) a += (totc[e]/(float)T_) * (totp[e]/(float)T_);
        g_aux[0] += (float)NE * a;
    }
}
__global__ void k_bucket() {
    int t = blockIdx.x*256 + threadIdx.x;
    if (t >= T_) return;
    for (int j = 0; j < 2; j++) {
        int e = g_ti[2*t + j];
        int pos = atomicAdd(&g_cnt[e], 1);
        g_rows[e*T_ + pos] = t;
        g_slot[2*t + j] = e*T_ + pos;
    }
}
__global__ void k_combine() {
    int t = blockIdx.x, tid = threadIdx.x;
    int s0 = g_slot[2*t], s1 = g_slot[2*t+1];
    float w0 = g_tw[2*t], w1 = g_tw[2*t+1];
    const float* y0 = g_yb + (size_t)s0*D_;
    const float* y1 = g_yb + (size_t)s1*D_;
    float* hr = g_h + (size_t)t*D_;
    for (int d = tid; d < D_; d += 256) hr[d] += w0*y0[d] + w1*y1[d];
}
__global__ void k_task(const float* __restrict__ tw, const float* __restrict__ tb, float* __restrict__ out) {
    int c = blockIdx.x, tid = threadIdx.x;
    __shared__ float sh[256];
    float s = 0.f;
    for (int d = tid; d < D_; d += 256) s += g_xn[d] * tw[(size_t)d*16 + c];
    sh[tid] = s; __syncthreads();
    for (int o = 128; o > 0; o >>= 1) { if (tid < o) sh[tid] += sh[tid+o]; __syncthreads(); }
    if (tid == 0) out[OUT_TASK + c] = sh[0] + tb[c];
}
__global__ void k_mean1() {
    int b = blockIdx.x, tid = threadIdx.x;
    const float* x = g_xn + (size_t)b*128*D_ + tid*4;
    float4 a = make_float4(0.f,0.f,0.f,0.f);
    for (int r = 0; r < 128; r++) {
        float4 v = *(const float4*)(x + (size_t)r*D_);
        a.x += v.x; a.y += v.y; a.z += v.z; a.w += v.w;
    }
    *(float4*)(g_mp + b*D_ + tid*4) = a;
}
__global__ void k_mean2() {
    int d = blockIdx.x*256 + threadIdx.x;
    float s = 0.f;
    for (int b = 0; b < 16; b++) s += g_mp[b*D_ + d];
    g_xm[d] = s / (float)T_;
}
__global__ void k_eval(const float* __restrict__ ew, const float* __restrict__ eb, float* __restrict__ out) {
    int c = blockIdx.x, tid = threadIdx.x;
    __shared__ float sh[256];
    float s = 0.f;
    for (int d = tid; d < D_; d += 256) s += g_xm[d] * ew[(size_t)d*8 + c];
    sh[tid] = s; __syncthreads();
    for (int o = 128; o > 0; o >>= 1) { if (tid < o) sh[tid] += sh[tid+o]; __syncthreads(); }
    if (tid == 0) out[OUT_EVAL + c] = sh[0] + eb[c];
}
__global__ void k_auxw(float* __restrict__ out) { out[OUT_AUX] = g_aux[0]; }

// ---------------- launch ----------------
extern "C" void kernel_launch(void* const* d_in, const int* in_sizes, int n_in,
                              void* d_out, int out_size) {
    const int*   ids     = (const int*)  d_in[0];
    const float* embed_W = (const float*)d_in[1];
    const float* n1      = (const float*)d_in[2];
    const float* n2      = (const float*)d_in[3];
    const float* wq      = (const float*)d_in[4];
    const float* wk      = (const float*)d_in[5];
    const float* wv      = (const float*)d_in[6];
    const float* wo      = (const float*)d_in[7];
    const float* rw      = (const float*)d_in[8];
    const float* w1      = (const float*)d_in[9];
    const float* w3      = (const float*)d_in[10];
    const float* w2      = (const float*)d_in[11];
    const float* normf   = (const float*)d_in[12];
    const float* lm      = (const float*)d_in[13];
    const float* tw      = (const float*)d_in[14];
    const float* tb      = (const float*)d_in[15];
    const float* ew      = (const float*)d_in[16];
    const float* eb      = (const float*)d_in[17];
    float* out = (float*)d_out;

    float *p_h, *p_xn, *p_qkv;
    bf16 *p_ah, *p_al;
    bf16 *p_cqh, *p_cql, *p_cwoh, *p_cwol, *p_c1h, *p_c1l, *p_c3h, *p_c3l, *p_c2h, *p_c2l, *p_clh, *p_cll;
    cudaGetSymbolAddress((void**)&p_h,    g_h);
    cudaGetSymbolAddress((void**)&p_xn,   g_xn);
    cudaGetSymbolAddress((void**)&p_qkv,  g_qkv);
    cudaGetSymbolAddress((void**)&p_ah,   g_ah);
    cudaGetSymbolAddress((void**)&p_al,   g_al);
    cudaGetSymbolAddress((void**)&p_cqh,  c_qkvh);
    cudaGetSymbolAddress((void**)&p_cql,  c_qkvl);
    cudaGetSymbolAddress((void**)&p_cwoh, c_woh);
    cudaGetSymbolAddress((void**)&p_cwol, c_wol);
    cudaGetSymbolAddress((void**)&p_c1h,  c_w1h);
    cudaGetSymbolAddress((void**)&p_c1l,  c_w1l);
    cudaGetSymbolAddress((void**)&p_c3h,  c_w3h);
    cudaGetSymbolAddress((void**)&p_c3l,  c_w3l);
    cudaGetSymbolAddress((void**)&p_c2h,  c_w2h);
    cudaGetSymbolAddress((void**)&p_c2l,  c_w2l);
    cudaGetSymbolAddress((void**)&p_clh,  c_lmh);
    cudaGetSymbolAddress((void**)&p_cll,  c_lml);

    cudaFuncSetAttribute(k_mma256,  cudaFuncAttributeMaxDynamicSharedMemorySize, SMEM_W);
    cudaFuncSetAttribute(k_moe_mma, cudaFuncAttributeMaxDynamicSharedMemorySize, SMEM_W);
    cudaFuncSetAttribute(k_avm,     cudaFuncAttributeMaxDynamicSharedMemorySize, SMEM_MMA128);
    cudaFuncSetAttribute(k_qk,      cudaFuncAttributeMaxDynamicSharedMemorySize, SMEM_QK);

    k_embed<<<T_, 256>>>(ids, embed_W);
    k_convqkv<<<dim3(1024, 6), 256>>>(wq, wk, wv);
    k_convw5<<<dim3(8192, 5), 256>>>(wo, w1, w3, w2, lm);

    for (int l = 0; l < NL; l++) {
        // attention
        k_rmssplit<<<T_, 256>>>(p_h, n1 + (size_t)l*D_, p_xn, p_ah, p_al);
        k_mma256<<<dim3(16, 6), 256, SMEM_W>>>(p_ah, p_al,
            p_cqh + (size_t)l*D_*QKV_, p_cql + (size_t)l*D_*QKV_, p_qkv, D_, QKV_, QKV_, 0);
        k_ropesplit<<<T_, 192>>>();
        k_qk<<<dim3(4, 4, 64), 256, SMEM_QK>>>();
        k_softmax<<<NCK*NH*CH/8, 256>>>();
        k_avm<<<dim3(4, 1, 64), 256, SMEM_MMA128>>>();   // writes bf16 hi/lo into g_ah/g_al
        k_mma256<<<dim3(16, 4), 256, SMEM_W>>>(p_ah, p_al,
            p_cwoh + (size_t)l*D_*D_, p_cwol + (size_t)l*D_*D_, p_h, D_, D_, D_, 1);

        // MoE
        k_rmssplit<<<T_, 256>>>(p_h, n2 + (size_t)l*D_, p_xn, p_ah, p_al);
        k_router<<<T_/8, 256>>>(rw + (size_t)l*D_*NE);
        k_aux<<<1, 256>>>();
        k_bucket<<<T_/256, 256>>>();
        k_moe_mma<<<dim3(16, 8, NE), 256, SMEM_W>>>(p_c1h + (size_t)l*NE*D_*F_, p_c1l + (size_t)l*NE*D_*F_, 0);
        k_moe_mma<<<dim3(16, 8, NE), 256, SMEM_W>>>(p_c3h + (size_t)l*NE*D_*F_, p_c3l + (size_t)l*NE*D_*F_, 1);
        k_moe_mma<<<dim3(16, 4, NE), 256, SMEM_W>>>(p_c2h + (size_t)l*NE*F_*D_, p_c2l + (size_t)l*NE*F_*D_, 2);
        k_combine<<<T_, 256>>>();
    }

    // final norm + heads
    k_rmssplit<<<T_, 256>>>(p_h, normf, p_xn, p_ah, p_al);
    k_mma256<<<dim3(16, NV/256), 256, SMEM_W>>>(p_ah, p_al, p_clh, p_cll, out, D_, NV, NV, 0);
    k_task<<<16, 256>>>(tw, tb, out);
    k_mean1<<<16, 256>>>();
    k_mean2<<<4, 256>>>();
    k_eval<<<8, 256>>>(ew, eb, out);
    k_auxw<<<1, 1>>>(out);
}